// round 16
// baseline (speedup 1.0000x reference)
#include <cuda_runtime.h>
#include <cuda_bf16.h>
#include <mma.h>
#include <cstdint>
using namespace nvcuda;
typedef __nv_bfloat16 bf16;

#define SQ 4096
#define DM 128
#define NH 4
#define NL 3
#define FFD 1024
#define NSPL 2
#define OFF_WQKV 0
#define OFF_WO   147456
#define OFF_W1   196608
#define OFF_W2   589824
#define OFF_FC1  983040
#define OFF_FC2  999424
#define WTOT     1015808

__device__ float g_x[SQ*DM];
__device__ bf16 g_xh[SQ*DM], g_xl[SQ*DM];
__device__ bf16 g_qh[SQ*3*DM];
__device__ bf16 g_f1h[SQ*FFD], g_f1l[SQ*FFD];
__device__ bf16 g_xnh[SQ*DM], g_xnl[SQ*DM];
__device__ bf16 g_wh[WTOT], g_wl[WTOT];
__device__ bf16 g_oat[NSPL*SQ*DM];
__device__ float g_psum[NSPL*NH*SQ];

__device__ __forceinline__ float ex2f(float x){ float y; asm("ex2.approx.f32 %0, %1;" : "=f"(y) : "f"(x)); return y; }
__device__ __forceinline__ uint32_t pack_hi(float a, float b) {
    return (uint32_t)__bfloat16_as_ushort(__float2bfloat16(a))
         | ((uint32_t)__bfloat16_as_ushort(__float2bfloat16(b)) << 16);
}
__device__ __forceinline__ uint32_t pack_lo(float a, float b) {
    float ar = a - __bfloat162float(__float2bfloat16(a));
    float br = b - __bfloat162float(__float2bfloat16(b));
    return pack_hi(ar, br);
}
__device__ __forceinline__ float bflo(uint32_t u){ return __bfloat162float(__ushort_as_bfloat16((unsigned short)(u & 0xFFFFu))); }
__device__ __forceinline__ float bfhi(uint32_t u){ return __bfloat162float(__ushort_as_bfloat16((unsigned short)(u >> 16))); }
__device__ __forceinline__ uint32_t smem_u32(const void* p) {
    uint32_t a;
    asm("{ .reg .u64 t; cvta.to.shared.u64 t, %1; cvt.u32.u64 %0, t; }" : "=r"(a) : "l"(p));
    return a;
}
#define CP_ASYNC16(sa,gp) asm volatile("cp.async.cg.shared.global [%0], [%1], 16;" :: "r"((uint32_t)(sa)), "l"(gp) : "memory")
#define CP_COMMIT() asm volatile("cp.async.commit_group;" ::: "memory")
#define CP_WAIT2() asm volatile("cp.async.wait_group 2;" ::: "memory")
#define CP_WAIT1() asm volatile("cp.async.wait_group 1;" ::: "memory")
#define CP_WAIT0() asm volatile("cp.async.wait_group 0;" ::: "memory")

__device__ __forceinline__ void mma16816(float* c, const uint32_t* a, uint32_t b0, uint32_t b1) {
    asm volatile("mma.sync.aligned.m16n8k16.row.col.f32.bf16.bf16.f32 "
        "{%0,%1,%2,%3},{%4,%5,%6,%7},{%8,%9},{%0,%1,%2,%3};"
        : "+f"(c[0]),"+f"(c[1]),"+f"(c[2]),"+f"(c[3])
        : "r"(a[0]),"r"(a[1]),"r"(a[2]),"r"(a[3]),"r"(b0),"r"(b1));
}
__device__ __forceinline__ void ldsm4(uint32_t* r, uint32_t a) {
    asm volatile("ldmatrix.sync.aligned.m8n8.x4.shared.b16 {%0,%1,%2,%3},[%4];"
        : "=r"(r[0]),"=r"(r[1]),"=r"(r[2]),"=r"(r[3]) : "r"(a));
}
__device__ __forceinline__ void ldsm4t(uint32_t* r, uint32_t a) {
    asm volatile("ldmatrix.sync.aligned.m8n8.x4.trans.shared.b16 {%0,%1,%2,%3},[%4];"
        : "=r"(r[0]),"=r"(r[1]),"=r"(r[2]),"=r"(r[3]) : "r"(a));
}

// ---------- prep ----------
__global__ void prep_kernel(const float* __restrict__ Wqkv, const float* __restrict__ Wo,
                            const float* __restrict__ W1, const float* __restrict__ W2,
                            const float* __restrict__ fc1W, const float* __restrict__ fc2W,
                            const float* __restrict__ src,
                            bf16* __restrict__ wh, bf16* __restrict__ wl,
                            float* __restrict__ x, bf16* __restrict__ xh, bf16* __restrict__ xl) {
    int i = blockIdx.x * 256 + threadIdx.x;
    if (i < WTOT) {
        const float* s; int base;
        if      (i < 196608) { if (i < 147456) { s=Wqkv; base=OFF_WQKV; } else { s=Wo; base=OFF_WO; } }
        else if (i < 983040) { if (i < 589824) { s=W1; base=OFF_W1; } else { s=W2; base=OFF_W2; } }
        else                 { if (i < 999424) { s=fc1W; base=OFF_FC1; } else { s=fc2W; base=OFF_FC2; } }
        float v = s[i - base];
        bf16 h = __float2bfloat16(v);
        wh[i] = h; wl[i] = __float2bfloat16(v - __bfloat162float(h));
    } else if (i < WTOT + SQ*DM) {
        int j = i - WTOT;
        float v = src[j]; x[j] = v;
        bf16 h = __float2bfloat16(v);
        xh[j] = h; xl[j] = __float2bfloat16(v - __bfloat162float(h));
    }
}

// ---------- FFN1 GEMM (128x128 tile, double buffered) ----------
#define GEMM_SMEM 84480
template<int EPI, bool SA, int OUTM>
__global__ __launch_bounds__(256)
void wg_gemm(const bf16* __restrict__ Ah, const bf16* __restrict__ Al,
             const bf16* __restrict__ Bh, const bf16* __restrict__ Bl,
             const float* __restrict__ bias,
             bf16* __restrict__ Ch, bf16* __restrict__ Cl, int N, int K) {
    extern __shared__ char smraw[];
    const int BUFB = (SA ? 4 : 3) * 10240;
    uint32_t sbase = smem_u32(smraw);
    float* Cs = (float*)smraw;
    const int tid = threadIdx.x, w = tid >> 5;
    const int wm = w >> 1, wn = w & 1;
    const int bm = blockIdx.y * 128, bn = blockIdx.x * 128;
    const int ldr = tid >> 1, lh = tid & 1;

    auto issue = [&](int kc, int bi) {
        uint32_t buf = sbase + bi * BUFB;
        int r = tid >> 1, c2 = (tid & 1) * 2;
        uint32_t d = buf + r * 80 + c2 * 16;
        const char* pa = (const char*)(Ah + (size_t)(bm + r) * K + kc) + c2 * 16;
        CP_ASYNC16(d, pa); CP_ASYNC16(d + 16, pa + 16);
        if (SA) {
            const char* pl = (const char*)(Al + (size_t)(bm + r) * K + kc) + c2 * 16;
            CP_ASYNC16(d + 10240, pl); CP_ASYNC16(d + 10240 + 16, pl + 16);
        }
        uint32_t boff = (SA ? 2 : 1) * 10240;
        const char* pb = (const char*)(Bh + (size_t)(bn + r) * K + kc) + c2 * 16;
        CP_ASYNC16(d + boff, pb); CP_ASYNC16(d + boff + 16, pb + 16);
        const char* pbl = (const char*)(Bl + (size_t)(bn + r) * K + kc) + c2 * 16;
        CP_ASYNC16(d + boff + 10240, pbl); CP_ASYNC16(d + boff + 10240 + 16, pbl + 16);
        CP_COMMIT();
    };

    wmma::fragment<wmma::accumulator,16,16,16,float> acc[2][4];
#pragma unroll
    for (int i=0;i<2;i++)
#pragma unroll
        for (int j=0;j<4;j++) wmma::fill_fragment(acc[i][j], 0.f);

    const int nk = K >> 5;
    issue(0, 0);
    for (int c = 0; c < nk; c++) {
        if (c + 1 < nk) { issue((c + 1) * 32, (c + 1) & 1); CP_WAIT1(); }
        else CP_WAIT0();
        __syncthreads();
        bf16* As  = (bf16*)(smraw + (c & 1) * BUFB);
        bf16* Als = As + 5120;
        bf16* Bs  = As + (SA ? 2 : 1) * 5120;
        bf16* Bls = Bs + 5120;
#pragma unroll
        for (int ks = 0; ks < 2; ks++) {
            wmma::fragment<wmma::matrix_a,16,16,16,bf16,wmma::row_major> fa[2], fal[2];
#pragma unroll
            for (int i=0;i<2;i++) {
                wmma::load_matrix_sync(fa[i], As + (wm*32+i*16)*40 + ks*16, 40);
                if (SA) wmma::load_matrix_sync(fal[i], Als + (wm*32+i*16)*40 + ks*16, 40);
            }
#pragma unroll
            for (int j=0;j<4;j++) {
                wmma::fragment<wmma::matrix_b,16,16,16,bf16,wmma::col_major> fb;
                wmma::load_matrix_sync(fb, Bs + (wn*64+j*16)*40 + ks*16, 40);
#pragma unroll
                for (int i=0;i<2;i++) wmma::mma_sync(acc[i][j], fa[i], fb, acc[i][j]);
                if (SA) {
#pragma unroll
                    for (int i=0;i<2;i++) wmma::mma_sync(acc[i][j], fal[i], fb, acc[i][j]);
                }
                wmma::load_matrix_sync(fb, Bls + (wn*64+j*16)*40 + ks*16, 40);
#pragma unroll
                for (int i=0;i<2;i++) wmma::mma_sync(acc[i][j], fa[i], fb, acc[i][j]);
            }
        }
        __syncthreads();
    }
#pragma unroll
    for (int i=0;i<2;i++)
#pragma unroll
        for (int j=0;j<4;j++)
            wmma::store_matrix_sync(Cs + (wm*32+i*16)*132 + wn*64 + j*16, acc[i][j], 132, wmma::mem_row_major);
    __syncthreads();

    const int row = bm + ldr, cb = lh * 64;
#pragma unroll
    for (int c0 = 0; c0 < 64; c0 += 8) {
        float v[8];
#pragma unroll
        for (int i=0;i<8;i++) {
            float xv = Cs[ldr*132 + cb + c0 + i] + bias[bn + cb + c0 + i];
            if (EPI==1) xv = fmaxf(xv, 0.f);
            v[i] = xv;
        }
        *(uint4*)(Ch + (size_t)row*N + bn + cb + c0) =
            make_uint4(pack_hi(v[0],v[1]),pack_hi(v[2],v[3]),pack_hi(v[4],v[5]),pack_hi(v[6],v[7]));
        if (OUTM == 2)
            *(uint4*)(Cl + (size_t)row*N + bn + cb + c0) =
                make_uint4(pack_lo(v[0],v[1]),pack_lo(v[2],v[3]),pack_lo(v[4],v[5]),pack_lo(v[6],v[7]));
    }
}

// ---------- QKV GEMM (64x128 tile, K=128, one-shot) ----------
#define GEMM64N_SMEM 102400
__global__ __launch_bounds__(256)
void wg_gemm64n(const bf16* __restrict__ Ah,
                const bf16* __restrict__ Bh, const bf16* __restrict__ Bl,
                const float* __restrict__ bias, bf16* __restrict__ Ch) {
    extern __shared__ char smraw[];
    const int K = 128, N = 384;
    const int BUFB = 25600;
    uint32_t sbase = smem_u32(smraw);
    float* Cs = (float*)smraw;
    const int tid = threadIdx.x, w = tid >> 5;
    const int wm = w >> 2, wn = w & 3;
    const int bm = blockIdx.y * 64, bn = blockIdx.x * 128;

    auto issue = [&](int kc, int bi) {
        uint32_t buf = sbase + bi * BUFB;
        int r = tid >> 2, c = tid & 3;
        CP_ASYNC16(buf + r * 80 + c * 16, (const char*)(Ah + (size_t)(bm + r) * K + kc) + c * 16);
        int r2 = tid >> 1, c2 = (tid & 1) * 2;
        uint32_t d2 = buf + 5120 + r2 * 80 + c2 * 16;
        const char* pb = (const char*)(Bh + (size_t)(bn + r2) * K + kc) + c2 * 16;
        CP_ASYNC16(d2, pb); CP_ASYNC16(d2 + 16, pb + 16);
        const char* pbl = (const char*)(Bl + (size_t)(bn + r2) * K + kc) + c2 * 16;
        CP_ASYNC16(d2 + 10240, pbl); CP_ASYNC16(d2 + 10240 + 16, pbl + 16);
        CP_COMMIT();
    };

    wmma::fragment<wmma::accumulator,16,16,16,float> acc[2][2];
#pragma unroll
    for (int i=0;i<2;i++)
#pragma unroll
        for (int j=0;j<2;j++) wmma::fill_fragment(acc[i][j], 0.f);

#pragma unroll
    for (int c = 0; c < 4; c++) issue(c * 32, c);
    CP_WAIT0();
    __syncthreads();
#pragma unroll
    for (int c = 0; c < 4; c++) {
        bf16* As  = (bf16*)(smraw + c * BUFB);
        bf16* Bs  = As + 2560;
        bf16* Bls = As + 7680;
#pragma unroll
        for (int ks = 0; ks < 2; ks++) {
            wmma::fragment<wmma::matrix_a,16,16,16,bf16,wmma::row_major> fa[2];
#pragma unroll
            for (int i=0;i<2;i++)
                wmma::load_matrix_sync(fa[i], As + (wm*32+i*16)*40 + ks*16, 40);
#pragma unroll
            for (int j=0;j<2;j++) {
                wmma::fragment<wmma::matrix_b,16,16,16,bf16,wmma::col_major> fb;
                wmma::load_matrix_sync(fb, Bs + (wn*32+j*16)*40 + ks*16, 40);
#pragma unroll
                for (int i=0;i<2;i++) wmma::mma_sync(acc[i][j], fa[i], fb, acc[i][j]);
                wmma::load_matrix_sync(fb, Bls + (wn*32+j*16)*40 + ks*16, 40);
#pragma unroll
                for (int i=0;i<2;i++) wmma::mma_sync(acc[i][j], fa[i], fb, acc[i][j]);
            }
        }
    }
    __syncthreads();
#pragma unroll
    for (int i=0;i<2;i++)
#pragma unroll
        for (int j=0;j<2;j++)
            wmma::store_matrix_sync(Cs + (wm*32+i*16)*132 + wn*32 + j*16, acc[i][j], 132, wmma::mem_row_major);
    __syncthreads();

    const int ldr = tid >> 2, q = tid & 3;
    const int row = bm + ldr, cb = q * 32;
#pragma unroll
    for (int c0 = 0; c0 < 32; c0 += 8) {
        float v[8];
#pragma unroll
        for (int i=0;i<8;i++) v[i] = Cs[ldr*132 + cb + c0 + i] + bias[bn + cb + c0 + i];
        *(uint4*)(Ch + (size_t)row*N + bn + cb + c0) =
            make_uint4(pack_hi(v[0],v[1]),pack_hi(v[2],v[3]),pack_hi(v[4],v[5]),pack_hi(v[6],v[7]));
    }
}

// ---------- O-proj: 16-row tiles (grid 256), fused per-head combine + residual + LN ----------
#define OPROJ_BUFB 21760
#define OPROJ_SMEM 87040
__global__ __launch_bounds__(256)
void wg_oproj(const bf16* __restrict__ opart, const float* __restrict__ spart,
              const bf16* __restrict__ Bh, const bf16* __restrict__ Bl,
              const float* __restrict__ bias, float* __restrict__ xres,
              const float* __restrict__ gam, const float* __restrict__ bet,
              bf16* __restrict__ outh, bf16* __restrict__ outl) {
    extern __shared__ char smraw[];
    const int K = 128;
    uint32_t sbase = smem_u32(smraw);
    float* Cs = (float*)smraw;
    const int tid = threadIdx.x, w = tid >> 5;
    const int bm = blockIdx.x * 16;

    // B (hi+lo) for all 4 K-chunks
#pragma unroll
    for (int c = 0; c < 4; c++) {
        uint32_t buf = sbase + c * OPROJ_BUFB;
        int r2 = tid >> 1, c2 = (tid & 1) * 2;
        uint32_t d2 = buf + 1280 + r2 * 80 + c2 * 16;
        const char* pb = (const char*)(Bh + (size_t)r2 * K + c * 32) + c2 * 16;
        CP_ASYNC16(d2, pb); CP_ASYNC16(d2 + 16, pb + 16);
        const char* pbl = (const char*)(Bl + (size_t)r2 * K + c * 32) + c2 * 16;
        CP_ASYNC16(d2 + 10240, pbl); CP_ASYNC16(d2 + 10240 + 16, pbl + 16);
        CP_COMMIT();
    }
    // per-head combine: each thread 8 cols of one row (16 rows x 16 thr/row)
    {
        int row = tid >> 4, cseg = (tid & 15) * 8;
        int rg = bm + row, h = cseg >> 5;
        float ssum = 0.f;
#pragma unroll
        for (int z = 0; z < NSPL; z++) ssum += spart[(z*NH + h)*SQ + rg];
        float inv = 1.f / ssum;
        float v[8];
#pragma unroll
        for (int i=0;i<8;i++) v[i] = 0.f;
#pragma unroll
        for (int z = 0; z < NSPL; z++) {
            uint4 a = *(const uint4*)(opart + ((size_t)z*SQ + rg)*DM + cseg);
            uint32_t u[4] = {a.x,a.y,a.z,a.w};
#pragma unroll
            for (int k=0;k<4;k++) { v[2*k] += bflo(u[k]); v[2*k+1] += bfhi(u[k]); }
        }
#pragma unroll
        for (int i=0;i<8;i++) v[i] *= inv;
        int chunk = cseg >> 5, off = cseg & 31;
        char* dst = smraw + chunk * OPROJ_BUFB + row * 80 + off * 2;
        *(uint4*)dst = make_uint4(pack_hi(v[0],v[1]),pack_hi(v[2],v[3]),pack_hi(v[4],v[5]),pack_hi(v[6],v[7]));
    }
    CP_WAIT0();
    __syncthreads();

    wmma::fragment<wmma::accumulator,16,16,16,float> acc;
    wmma::fill_fragment(acc, 0.f);
#pragma unroll
    for (int c = 0; c < 4; c++) {
        bf16* As  = (bf16*)(smraw + c * OPROJ_BUFB);
        bf16* Bs  = (bf16*)((char*)As + 1280);
        bf16* Bls = Bs + 5120;
#pragma unroll
        for (int ks = 0; ks < 2; ks++) {
            wmma::fragment<wmma::matrix_a,16,16,16,bf16,wmma::row_major> fa;
            wmma::load_matrix_sync(fa, As + ks*16, 40);
            wmma::fragment<wmma::matrix_b,16,16,16,bf16,wmma::col_major> fb;
            wmma::load_matrix_sync(fb, Bs + (w*16)*40 + ks*16, 40);
            wmma::mma_sync(acc, fa, fb, acc);
            wmma::load_matrix_sync(fb, Bls + (w*16)*40 + ks*16, 40);
            wmma::mma_sync(acc, fa, fb, acc);
        }
    }
    __syncthreads();
    wmma::store_matrix_sync(Cs + w*16, acc, 132, wmma::mem_row_major);
    __syncthreads();

    const int row2 = tid >> 4, cseg = (tid & 15) * 8;
    const int rg = bm + row2;
    float v[8];
#pragma unroll
    for (int i=0;i<8;i++) v[i] = Cs[row2*132 + cseg + i] + bias[cseg + i];
    float s = 0.f, s2 = 0.f;
#pragma unroll
    for (int i=0;i<8;i++) { v[i] += xres[(size_t)rg*DM + cseg + i]; s += v[i]; }
#pragma unroll
    for (int i=0;i<8;i++) s2 += v[i]*v[i];
    s  += __shfl_xor_sync(~0u, s, 1);  s  += __shfl_xor_sync(~0u, s, 2);
    s  += __shfl_xor_sync(~0u, s, 4);  s  += __shfl_xor_sync(~0u, s, 8);
    s2 += __shfl_xor_sync(~0u, s2, 1); s2 += __shfl_xor_sync(~0u, s2, 2);
    s2 += __shfl_xor_sync(~0u, s2, 4); s2 += __shfl_xor_sync(~0u, s2, 8);
    float mean = s * (1.f/DM);
    float var = s2 * (1.f/DM) - mean*mean;
    float inv = rsqrtf(var + 1e-5f);
#pragma unroll
    for (int i=0;i<8;i++) v[i] = (v[i] - mean) * inv * gam[cseg+i] + bet[cseg+i];
    float4* dx = (float4*)(xres + (size_t)rg*DM + cseg);
    dx[0] = make_float4(v[0],v[1],v[2],v[3]);
    dx[1] = make_float4(v[4],v[5],v[6],v[7]);
    *(uint4*)(outh + (size_t)rg*DM + cseg) =
        make_uint4(pack_hi(v[0],v[1]),pack_hi(v[2],v[3]),pack_hi(v[4],v[5]),pack_hi(v[6],v[7]));
    *(uint4*)(outl + (size_t)rg*DM + cseg) =
        make_uint4(pack_lo(v[0],v[1]),pack_lo(v[2],v[3]),pack_lo(v[4],v[5]),pack_lo(v[6],v[7]));
}

// ---------- FFN2 GEMM (32x128 tile, K=1024, 3-stage) + residual + LN ----------
#define GEMM32_SMEM 76800
__global__ __launch_bounds__(256)
void wg_ffn2(const bf16* __restrict__ Ah, const bf16* __restrict__ Al,
             const bf16* __restrict__ Bh, const bf16* __restrict__ Bl,
             const float* __restrict__ bias, float* __restrict__ xres,
             const float* __restrict__ gam, const float* __restrict__ bet,
             bf16* __restrict__ outh, bf16* __restrict__ outl) {
    extern __shared__ char smraw[];
    const int K = 1024;
    const int AB = 5120, BUFB = 25600;
    uint32_t sbase = smem_u32(smraw);
    float* Cs = (float*)smraw;
    const int tid = threadIdx.x, w = tid >> 5;
    const int wm = w >> 2, wn = w & 3;
    const int bm = blockIdx.x * 32;

    auto issue = [&](int kc, int bi) {
        uint32_t buf = sbase + bi * BUFB;
        int m = (tid < 128) ? 0 : 1;
        const bf16* Asrc = m ? Al : Ah;
        int tt = tid & 127;
        int r = tt >> 2, c = tt & 3;
        CP_ASYNC16(buf + m * 2560 + r * 80 + c * 16,
                   (const char*)(Asrc + (size_t)(bm + r) * K + kc) + c * 16);
        int r2 = tid >> 1, c2 = (tid & 1) * 2;
        uint32_t d2 = buf + AB + r2 * 80 + c2 * 16;
        const char* pb = (const char*)(Bh + (size_t)r2 * K + kc) + c2 * 16;
        CP_ASYNC16(d2, pb); CP_ASYNC16(d2 + 16, pb + 16);
        const char* pbl = (const char*)(Bl + (size_t)r2 * K + kc) + c2 * 16;
        CP_ASYNC16(d2 + 10240, pbl); CP_ASYNC16(d2 + 10240 + 16, pbl + 16);
        CP_COMMIT();
    };

    wmma::fragment<wmma::accumulator,16,16,16,float> acc[2];
    wmma::fill_fragment(acc[0], 0.f);
    wmma::fill_fragment(acc[1], 0.f);

    const int nk = 32;
    issue(0, 0); issue(32, 1);
    for (int c = 0; c < nk; c++) {
        if (c + 2 < nk) issue((c + 2) * 32, (c + 2) % 3);
        if (c + 1 < nk) CP_WAIT2(); else CP_WAIT0();
        __syncthreads();
        bf16* As  = (bf16*)(smraw + (c % 3) * BUFB);
        bf16* Als = As + 1280;
        bf16* Bs  = (bf16*)((char*)As + AB);
        bf16* Bls = Bs + 5120;
#pragma unroll
        for (int ks = 0; ks < 2; ks++) {
            wmma::fragment<wmma::matrix_a,16,16,16,bf16,wmma::row_major> fa, fal;
            wmma::load_matrix_sync(fa, As + (wm*16)*40 + ks*16, 40);
            wmma::load_matrix_sync(fal, Als + (wm*16)*40 + ks*16, 40);
#pragma unroll
            for (int j=0;j<2;j++) {
                wmma::fragment<wmma::matrix_b,16,16,16,bf16,wmma::col_major> fb;
                wmma::load_matrix_sync(fb, Bs + (wn*32+j*16)*40 + ks*16, 40);
                wmma::mma_sync(acc[j], fa, fb, acc[j]);
                wmma::mma_sync(acc[j], fal, fb, acc[j]);
                wmma::load_matrix_sync(fb, Bls + (wn*32+j*16)*40 + ks*16, 40);
                wmma::mma_sync(acc[j], fa, fb, acc[j]);
            }
        }
        __syncthreads();
    }
#pragma unroll
    for (int j=0;j<2;j++)
        wmma::store_matrix_sync(Cs + (wm*16)*132 + wn*32 + j*16, acc[j], 132, wmma::mem_row_major);
    __syncthreads();

    const int ldr = tid >> 3, q = tid & 7;
    const int row = bm + ldr, cb = q * 16;
    float v[16];
#pragma unroll
    for (int i=0;i<16;i++) v[i] = Cs[ldr*132 + cb + i] + bias[cb + i];
    float s = 0.f, s2 = 0.f;
#pragma unroll
    for (int i=0;i<16;i++) { v[i] += xres[(size_t)row*DM + cb + i]; s += v[i]; }
#pragma unroll
    for (int i=0;i<16;i++) s2 += v[i]*v[i];
    s  += __shfl_xor_sync(~0u, s, 1);  s  += __shfl_xor_sync(~0u, s, 2);  s  += __shfl_xor_sync(~0u, s, 4);
    s2 += __shfl_xor_sync(~0u, s2, 1); s2 += __shfl_xor_sync(~0u, s2, 2); s2 += __shfl_xor_sync(~0u, s2, 4);
    float mean = s * (1.f/DM);
    float var = s2 * (1.f/DM) - mean*mean;
    float inv = rsqrtf(var + 1e-5f);
#pragma unroll
    for (int i=0;i<16;i++) v[i] = (v[i] - mean) * inv * gam[cb+i] + bet[cb+i];
    float4* dx = (float4*)(xres + (size_t)row*DM + cb);
#pragma unroll
    for (int i=0;i<4;i++) dx[i] = make_float4(v[4*i],v[4*i+1],v[4*i+2],v[4*i+3]);
#pragma unroll
    for (int c0 = 0; c0 < 16; c0 += 8) {
        *(uint4*)(outh + (size_t)row*DM + cb + c0) =
            make_uint4(pack_hi(v[c0],v[c0+1]),pack_hi(v[c0+2],v[c0+3]),pack_hi(v[c0+4],v[c0+5]),pack_hi(v[c0+6],v[c0+7]));
        *(uint4*)(outl + (size_t)row*DM + cb + c0) =
            make_uint4(pack_lo(v[c0],v[c0+1]),pack_lo(v[c0+2],v[c0+3]),pack_lo(v[c0+4],v[c0+5]),pack_lo(v[c0+6],v[c0+7]));
    }
}

// ---------- fused fc1 + fc2 + rownorm ----------
#define FC_SMEM 184320
__global__ __launch_bounds__(256)
void wg_fc(const bf16* __restrict__ xh, const bf16* __restrict__ xl,
           const bf16* __restrict__ B1h, const bf16* __restrict__ B1l,
           const float* __restrict__ b1,
           const bf16* __restrict__ B2h, const bf16* __restrict__ B2l,
           const float* __restrict__ b2,
           bf16* __restrict__ outh, bf16* __restrict__ outl) {
    extern __shared__ char smraw[];
    const int K = 128;
    uint32_t sbase = smem_u32(smraw);
    float* Cs = (float*)smraw;
    const int tid = threadIdx.x, w = tid >> 5;
    const int wm = w >> 2, wn = w & 3;
    const int bm = blockIdx.x * 32;

#pragma unroll
    for (int c = 0; c < 4; c++) {
        int m = (tid < 128) ? 0 : 1;
        const bf16* Asrc = m ? xl : xh;
        int tt = tid & 127;
        int r = tt >> 2, cc = tt & 3;
        CP_ASYNC16(sbase + c*5120 + m*2560 + r*80 + cc*16,
                   (const char*)(Asrc + (size_t)(bm + r) * K + c*32) + cc*16);
        int r2 = tid >> 1, c2 = (tid & 1) * 2;
        uint32_t d1 = sbase + 20480 + c*20480 + r2*80 + c2*16;
        const char* p1 = (const char*)(B1h + (size_t)r2 * K + c*32) + c2*16;
        CP_ASYNC16(d1, p1); CP_ASYNC16(d1 + 16, p1 + 16);
        const char* p1l = (const char*)(B1l + (size_t)r2 * K + c*32) + c2*16;
        CP_ASYNC16(d1 + 10240, p1l); CP_ASYNC16(d1 + 10240 + 16, p1l + 16);
        uint32_t d2 = sbase + 102400 + c*20480 + r2*80 + c2*16;
        const char* p2 = (const char*)(B2h + (size_t)r2 * K + c*32) + c2*16;
        CP_ASYNC16(d2, p2); CP_ASYNC16(d2 + 16, p2 + 16);
        const char* p2l = (const char*)(B2l + (size_t)r2 * K + c*32) + c2*16;
        CP_ASYNC16(d2 + 10240, p2l); CP_ASYNC16(d2 + 10240 + 16, p2l + 16);
        CP_COMMIT();
    }
    CP_WAIT0();
    __syncthreads();

    wmma::fragment<wmma::accumulator,16,16,16,float> acc[2];
    wmma::fill_fragment(acc[0], 0.f);
    wmma::fill_fragment(acc[1], 0.f);
#pragma unroll
    for (int c = 0; c < 4; c++) {
        bf16* As  = (bf16*)(smraw + c*5120);
        bf16* Als = As + 1280;
        bf16* Bs  = (bf16*)(smraw + 20480 + c*20480);
        bf16* Bls = Bs + 5120;
#pragma unroll
        for (int ks = 0; ks < 2; ks++) {
            wmma::fragment<wmma::matrix_a,16,16,16,bf16,wmma::row_major> fa, fal;
            wmma::load_matrix_sync(fa, As + (wm*16)*40 + ks*16, 40);
            wmma::load_matrix_sync(fal, Als + (wm*16)*40 + ks*16, 40);
#pragma unroll
            for (int j=0;j<2;j++) {
                wmma::fragment<wmma::matrix_b,16,16,16,bf16,wmma::col_major> fb;
                wmma::load_matrix_sync(fb, Bs + (wn*32+j*16)*40 + ks*16, 40);
                wmma::mma_sync(acc[j], fa, fb, acc[j]);
                wmma::mma_sync(acc[j], fal, fb, acc[j]);
                wmma::load_matrix_sync(fb, Bls + (wn*32+j*16)*40 + ks*16, 40);
                wmma::mma_sync(acc[j], fa, fb, acc[j]);
            }
        }
    }
    __syncthreads();
#pragma unroll
    for (int j=0;j<2;j++)
        wmma::store_matrix_sync(Cs + (wm*16)*132 + wn*32 + j*16, acc[j], 132, wmma::mem_row_major);
    __syncthreads();

    {
        int row = tid >> 3, q = tid & 7;
        int cb = q * 16;
        float v[16];
#pragma unroll
        for (int i=0;i<16;i++) v[i] = fmaxf(Cs[row*132 + cb + i] + b1[cb + i], 0.f);
        int chunk = cb >> 5, off = cb & 31;
        char* dh = smraw + 20480 + chunk*2560 + row*80 + off*2;
        char* dl = smraw + 30720 + chunk*2560 + row*80 + off*2;
        *(uint4*)dh = make_uint4(pack_hi(v[0],v[1]),pack_hi(v[2],v[3]),pack_hi(v[4],v[5]),pack_hi(v[6],v[7]));
        *(uint4*)(dh+16) = make_uint4(pack_hi(v[8],v[9]),pack_hi(v[10],v[11]),pack_hi(v[12],v[13]),pack_hi(v[14],v[15]));
        *(uint4*)dl = make_uint4(pack_lo(v[0],v[1]),pack_lo(v[2],v[3]),pack_lo(v[4],v[5]),pack_lo(v[6],v[7]));
        *(uint4*)(dl+16) = make_uint4(pack_lo(v[8],v[9]),pack_lo(v[10],v[11]),pack_lo(v[12],v[13]),pack_lo(v[14],v[15]));
    }
    __syncthreads();

    wmma::fill_fragment(acc[0], 0.f);
    wmma::fill_fragment(acc[1], 0.f);
#pragma unroll
    for (int c = 0; c < 4; c++) {
        bf16* As  = (bf16*)(smraw + 20480 + c*2560);
        bf16* Als = (bf16*)(smraw + 30720 + c*2560);
        bf16* Bs  = (bf16*)(smraw + 102400 + c*20480);
        bf16* Bls = Bs + 5120;
#pragma unroll
        for (int ks = 0; ks < 2; ks++) {
            wmma::fragment<wmma::matrix_a,16,16,16,bf16,wmma::row_major> fa, fal;
            wmma::load_matrix_sync(fa, As + (wm*16)*40 + ks*16, 40);
            wmma::load_matrix_sync(fal, Als + (wm*16)*40 + ks*16, 40);
#pragma unroll
            for (int j=0;j<2;j++) {
                wmma::fragment<wmma::matrix_b,16,16,16,bf16,wmma::col_major> fb;
                wmma::load_matrix_sync(fb, Bs + (wn*32+j*16)*40 + ks*16, 40);
                wmma::mma_sync(acc[j], fa, fb, acc[j]);
                wmma::mma_sync(acc[j], fal, fb, acc[j]);
                wmma::load_matrix_sync(fb, Bls + (wn*32+j*16)*40 + ks*16, 40);
                wmma::mma_sync(acc[j], fa, fb, acc[j]);
            }
        }
    }
    __syncthreads();
#pragma unroll
    for (int j=0;j<2;j++)
        wmma::store_matrix_sync(Cs + (wm*16)*132 + wn*32 + j*16, acc[j], 132, wmma::mem_row_major);
    __syncthreads();

    {
        int row = tid >> 3, q = tid & 7;
        int rg = bm + row, cb = q * 16;
        float v[16];
#pragma unroll
        for (int i=0;i<16;i++) v[i] = Cs[row*132 + cb + i] + b2[cb + i];
        float s2 = 0.f;
#pragma unroll
        for (int i=0;i<16;i++) s2 += v[i]*v[i];
        s2 += __shfl_xor_sync(~0u, s2, 1); s2 += __shfl_xor_sync(~0u, s2, 2); s2 += __shfl_xor_sync(~0u, s2, 4);
        float inv = rsqrtf(s2);
#pragma unroll
        for (int i=0;i<16;i++) v[i] *= inv;
#pragma unroll
        for (int c0 = 0; c0 < 16; c0 += 8) {
            *(uint4*)(outh + (size_t)rg*DM + cb + c0) =
                make_uint4(pack_hi(v[c0],v[c0+1]),pack_hi(v[c0+2],v[c0+3]),pack_hi(v[c0+4],v[c0+5]),pack_hi(v[c0+6],v[c0+7]));
            *(uint4*)(outl + (size_t)rg*DM + cb + c0) =
                make_uint4(pack_lo(v[c0],v[c0+1]),pack_lo(v[c0+2],v[c0+3]),pack_lo(v[c0+4],v[c0+5]),pack_lo(v[c0+6],v[c0+7]));
        }
    }
}

// ---------- Gram (triangular, 2 products: hi*hi + hi*lo) ----------
#define GRAM_BUFB 30720
#define GRAM_SMEM 67584
__global__ __launch_bounds__(256)
void gram_gemm(const bf16* __restrict__ Ah, const bf16* __restrict__ Al,
               float* __restrict__ Cf) {
    extern __shared__ char smraw[];
    uint32_t sbase = smem_u32(smraw);
    float* Cs = (float*)smraw;
    const int tid = threadIdx.x, w = tid >> 5;
    const int wm = w >> 1, wn = w & 1;
    int i = blockIdx.x;
    int tm = (int)((sqrtf(8.f*i + 1.f) - 1.f) * 0.5f);
    while ((tm+1)*(tm+2)/2 <= i) tm++;
    while (tm*(tm+1)/2 > i) tm--;
    int tn = i - tm*(tm+1)/2;
    const int bm = tm * 128, bn = tn * 128;
    const int K = DM, N = SQ;
    const int ldr = tid >> 1, lh = tid & 1;

    auto issue = [&](int kc, int bi) {
        uint32_t buf = sbase + bi * GRAM_BUFB;
        int r = tid >> 1, c2 = (tid & 1) * 2;
        uint32_t d = buf + r * 80 + c2 * 16;
        const char* pa = (const char*)(Ah + (size_t)(bm + r) * K + kc) + c2 * 16;
        CP_ASYNC16(d, pa); CP_ASYNC16(d + 16, pa + 16);
        const char* pb = (const char*)(Ah + (size_t)(bn + r) * K + kc) + c2 * 16;
        CP_ASYNC16(d + 10240, pb); CP_ASYNC16(d + 10240 + 16, pb + 16);
        const char* pbl = (const char*)(Al + (size_t)(bn + r) * K + kc) + c2 * 16;
        CP_ASYNC16(d + 20480, pbl); CP_ASYNC16(d + 20480 + 16, pbl + 16);
        CP_COMMIT();
    };

    wmma::fragment<wmma::accumulator,16,16,16,float> acc[2][4];
#pragma unroll
    for (int a=0;a<2;a++)
#pragma unroll
        for (int j=0;j<4;j++) wmma::fill_fragment(acc[a][j], 0.f);

    issue(0, 0);
    for (int c = 0; c < 4; c++) {
        if (c < 3) { issue((c + 1) * 32, (c + 1) & 1); CP_WAIT1(); }
        else CP_WAIT0();
        __syncthreads();
        bf16* As  = (bf16*)(smraw + (c & 1) * GRAM_BUFB);
        bf16* Bs  = As + 5120;
        bf16* Bls = As + 10240;
#pragma unroll
        for (int ks = 0; ks < 2; ks++) {
            wmma::fragment<wmma::matrix_a,16,16,16,bf16,wmma::row_major> fa[2];
#pragma unroll
            for (int a=0;a<2;a++)
                wmma::load_matrix_sync(fa[a], As + (wm*32+a*16)*40 + ks*16, 40);
#pragma unroll
            for (int j=0;j<4;j++) {
                wmma::fragment<wmma::matrix_b,16,16,16,bf16,wmma::col_major> fb;
                wmma::load_matrix_sync(fb, Bs + (wn*64+j*16)*40 + ks*16, 40);
#pragma unroll
                for (int a=0;a<2;a++) wmma::mma_sync(acc[a][j], fa[a], fb, acc[a][j]);
                wmma::load_matrix_sync(fb, Bls + (wn*64+j*16)*40 + ks*16, 40);
#pragma unroll
                for (int a=0;a<2;a++) wmma::mma_sync(acc[a][j], fa[a], fb, acc[a][j]);
            }
        }
        __syncthreads();
    }
#pragma unroll
    for (int a=0;a<2;a++)
#pragma unroll
        for (int j=0;j<4;j++)
            wmma::store_matrix_sync(Cs + (wm*32+a*16)*132 + wn*64 + j*16, acc[a][j], 132, wmma::mem_row_major);
    __syncthreads();

    const int cb = lh * 64;
#pragma unroll
    for (int c0 = 0; c0 < 64; c0 += 4) {
        float4 v;
        v.x = fmaxf(Cs[ldr*132 + cb + c0 + 0], 1e-6f);
        v.y = fmaxf(Cs[ldr*132 + cb + c0 + 1], 1e-6f);
        v.z = fmaxf(Cs[ldr*132 + cb + c0 + 2], 1e-6f);
        v.w = fmaxf(Cs[ldr*132 + cb + c0 + 3], 1e-6f);
        *(float4*)(Cf + (size_t)(bm + ldr)*N + bn + cb + c0) = v;
    }
    if (bm != bn) {
#pragma unroll
        for (int c0 = 0; c0 < 64; c0 += 4) {
            float4 v;
            v.x = fmaxf(Cs[(cb + c0 + 0)*132 + ldr], 1e-6f);
            v.y = fmaxf(Cs[(cb + c0 + 1)*132 + ldr], 1e-6f);
            v.z = fmaxf(Cs[(cb + c0 + 2)*132 + ldr], 1e-6f);
            v.w = fmaxf(Cs[(cb + c0 + 3)*132 + ldr], 1e-6f);
            *(float4*)(Cf + (size_t)(bn + ldr)*N + bm + cb + c0) = v;
        }
    }
}

// ---------- FA2 attention, split-K (2 splits), bf16 partials ----------
#define ATTN_SMEM 51200
__global__ __launch_bounds__(256)
void fa_attn(const bf16* __restrict__ q, bf16* __restrict__ opart, float* __restrict__ spart) {
    extern __shared__ char smraw[];
    uint32_t sb = smem_u32(smraw);
    const uint32_t Qs = sb, K0 = sb + 10240, V0 = sb + 30720;
    const int tid = threadIdx.x, w = tid >> 5, lane = tid & 31;
    const int g = lane >> 2, t = lane & 3;
    const int qt = blockIdx.x, h = blockIdx.y, z = blockIdx.z;
    const int kt0 = z * 16;
    const float C = 0.2550368953428811f;

    auto issue_kv = [&](int kt, int bi) {
        int r = tid >> 1, c2 = (tid & 1) * 2;
        const char* srck = (const char*)(q + (size_t)(kt*128 + r) * 384 + 128 + h*32) + c2*16;
        const char* srcv = (const char*)(q + (size_t)(kt*128 + r) * 384 + 256 + h*32) + c2*16;
        uint32_t kd = K0 + bi*10240 + r*80 + c2*16;
        uint32_t vd = V0 + bi*10240 + r*80 + c2*16;
        CP_ASYNC16(kd, srck); CP_ASYNC16(kd+16, srck+16);
        CP_ASYNC16(vd, srcv); CP_ASYNC16(vd+16, srcv+16);
        CP_COMMIT();
    };

    {
        int r = tid >> 1, c2 = (tid & 1) * 2;
        const char* srcq = (const char*)(q + (size_t)(qt*128 + r) * 384 + h*32) + c2*16;
        uint32_t qd = Qs + r*80 + c2*16;
        CP_ASYNC16(qd, srcq); CP_ASYNC16(qd+16, srcq+16);
        CP_COMMIT();
    }
    issue_kv(kt0, 0);

    uint32_t qf[2][4];
    float oacc[4][4];
#pragma unroll
    for (int i=0;i<4;i++)
#pragma unroll
        for (int j=0;j<4;j++) oacc[i][j] = 0.f;
    float sum_lo = 0.f, sum_hi = 0.f;

    for (int ki = 0; ki < 16; ki++) {
        int b = ki & 1;
        if (ki < 15) { issue_kv(kt0 + ki + 1, b ^ 1); CP_WAIT1(); }
        else CP_WAIT0();
        __syncthreads();
        if (ki == 0) {
#pragma unroll
            for (int s = 0; s < 2; s++) {
                uint32_t a = Qs + (uint32_t)(w*16 + ((lane>>3)&1)*8 + (lane&7))*80
                           + (uint32_t)(s*16 + (lane>>4)*8)*2;
                ldsm4(qf[s], a);
            }
        }
        uint32_t ks = K0 + b*10240, vs = V0 + b*10240;
#pragma unroll
        for (int j2 = 0; j2 < 8; j2++) {
            float sa[2][4] = {{0.f,0.f,0.f,0.f},{0.f,0.f,0.f,0.f}};
#pragma unroll
            for (int jj = 0; jj < 2; jj++) {
                int j = j2 * 2 + jj;
                uint32_t kf[4];
                uint32_t ka = ks + (uint32_t)(j*8 + (lane&7))*80 + (uint32_t)((lane>>3)*8)*2;
                ldsm4(kf, ka);
                mma16816(sa[jj], qf[0], kf[0], kf[1]);
                mma16816(sa[jj], qf[1], kf[2], kf[3]);
            }
            float p0 = ex2f(sa[0][0]*C), p1 = ex2f(sa[0][1]*C);
            float p2 = ex2f(sa[0][2]*C), p3 = ex2f(sa[0][3]*C);
            float p4 = ex2f(sa[1][0]*C), p5 = ex2f(sa[1][1]*C);
            float p6 = ex2f(sa[1][2]*C), p7 = ex2f(sa[1][3]*C);
            sum_lo += p0 + p1 + p4 + p5;
            sum_hi += p2 + p3 + p6 + p7;
            uint32_t af[4] = { pack_hi(p0,p1), pack_hi(p2,p3), pack_hi(p4,p5), pack_hi(p6,p7) };
#pragma unroll
            for (int half = 0; half < 2; half++) {
                uint32_t vf[4];
                uint32_t va = vs + (uint32_t)(j2*16 + ((lane>>3)&1)*8 + (lane&7))*80
                            + (uint32_t)((half*2 + (lane>>4))*8)*2;
                ldsm4t(vf, va);
                mma16816(oacc[half*2],     af, vf[0], vf[1]);
                mma16816(oacc[half*2 + 1], af, vf[2], vf[3]);
            }
        }
        __syncthreads();
    }
    sum_lo += __shfl_xor_sync(~0u, sum_lo, 1); sum_lo += __shfl_xor_sync(~0u, sum_lo, 2);
    sum_hi += __shfl_xor_sync(~0u, sum_hi, 1); sum_hi += __shfl_xor_sync(~0u, sum_hi, 2);
    int rlo = qt*128 + w*16 + g, rhi = rlo + 8;
    if (t == 0) {
        spart[(z*NH + h)*SQ + rlo] = sum_lo;
        spart[(z*NH + h)*SQ + rhi] = sum_hi;
    }
    bf16* oz = opart + (size_t)z*SQ*DM;
#pragma unroll
    for (int jd = 0; jd < 4; jd++) {
        *(uint32_t*)(oz + (size_t)rlo*DM + h*32 + jd*8 + 2*t) = pack_hi(oacc[jd][0], oacc[jd][1]);
        *(uint32_t*)(oz + (size_t)rhi*DM + h*32 + jd*8 + 2*t) = pack_hi(oacc[jd][2], oacc[jd][3]);
    }
}

// ---------- launch ----------
extern "C" void kernel_launch(void* const* d_in, const int* in_sizes, int n_in,
                              void* d_out, int out_size) {
    const float* src  = (const float*)d_in[0];
    const float* Wqkv = (const float*)d_in[1];
    const float* bqkv = (const float*)d_in[2];
    const float* Wo   = (const float*)d_in[3];
    const float* bo   = (const float*)d_in[4];
    const float* ln1g = (const float*)d_in[5];
    const float* ln1b = (const float*)d_in[6];
    const float* W1   = (const float*)d_in[7];
    const float* b1   = (const float*)d_in[8];
    const float* W2   = (const float*)d_in[9];
    const float* b2   = (const float*)d_in[10];
    const float* ln2g = (const float*)d_in[11];
    const float* ln2b = (const float*)d_in[12];
    const float* fc1W = (const float*)d_in[13];
    const float* fc1b = (const float*)d_in[14];
    const float* fc2W = (const float*)d_in[15];
    const float* fc2b = (const float*)d_in[16];
    float* out = (float*)d_out;

    float *x, *psum; bf16 *xh, *xl, *qh, *f1h, *f1l, *xnh, *xnl, *wh, *wl, *oat;
    cudaGetSymbolAddress((void**)&x, g_x);
    cudaGetSymbolAddress((void**)&xh, g_xh);   cudaGetSymbolAddress((void**)&xl, g_xl);
    cudaGetSymbolAddress((void**)&qh, g_qh);
    cudaGetSymbolAddress((void**)&f1h, g_f1h); cudaGetSymbolAddress((void**)&f1l, g_f1l);
    cudaGetSymbolAddress((void**)&xnh, g_xnh); cudaGetSymbolAddress((void**)&xnl, g_xnl);
    cudaGetSymbolAddress((void**)&wh, g_wh);   cudaGetSymbolAddress((void**)&wl, g_wl);
    cudaGetSymbolAddress((void**)&oat, g_oat); cudaGetSymbolAddress((void**)&psum, g_psum);

    cudaFuncSetAttribute(wg_gemm<1,true,2>,  cudaFuncAttributeMaxDynamicSharedMemorySize, GEMM_SMEM);
    cudaFuncSetAttribute(wg_gemm64n,         cudaFuncAttributeMaxDynamicSharedMemorySize, GEMM64N_SMEM);
    cudaFuncSetAttribute(wg_oproj,           cudaFuncAttributeMaxDynamicSharedMemorySize, OPROJ_SMEM);
    cudaFuncSetAttribute(wg_ffn2,            cudaFuncAttributeMaxDynamicSharedMemorySize, GEMM32_SMEM);
    cudaFuncSetAttribute(wg_fc,              cudaFuncAttributeMaxDynamicSharedMemorySize, FC_SMEM);
    cudaFuncSetAttribute(gram_gemm, cudaFuncAttributeMaxDynamicSharedMemorySize, GRAM_SMEM);
    cudaFuncSetAttribute(fa_attn, cudaFuncAttributeMaxDynamicSharedMemorySize, ATTN_SMEM);

    prep_kernel<<<(WTOT + SQ*DM)/256, 256>>>(Wqkv, Wo, W1, W2, fc1W, fc2W, src,
                                             wh, wl, x, xh, xl);

    for (int l = 0; l < NL; l++) {
        wg_gemm64n<<<dim3(3,64),256,GEMM64N_SMEM>>>(
            xh, wh+OFF_WQKV+(size_t)l*49152, wl+OFF_WQKV+(size_t)l*49152,
            bqkv + l*384, qh);
        fa_attn<<<dim3(32,NH,NSPL),256,ATTN_SMEM>>>(qh, oat, psum);
        wg_oproj<<<256,256,OPROJ_SMEM>>>(
            oat, psum, wh+OFF_WO+(size_t)l*16384, wl+OFF_WO+(size_t)l*16384,
            bo + l*DM, x, ln1g + l*DM, ln1b + l*DM, xh, xl);
        wg_gemm<1,true,2><<<dim3(8,32),256,GEMM_SMEM>>>(
            xh, xl, wh+OFF_W1+(size_t)l*131072, wl+OFF_W1+(size_t)l*131072,
            b1 + l*FFD, f1h, f1l, FFD, 128);
        wg_ffn2<<<128,256,GEMM32_SMEM>>>(
            f1h, f1l, wh+OFF_W2+(size_t)l*131072, wl+OFF_W2+(size_t)l*131072,
            b2 + l*DM, x, ln2g + l*DM, ln2b + l*DM, xh, xl);
    }
    wg_fc<<<128,256,FC_SMEM>>>(xh, xl, wh+OFF_FC1, wl+OFF_FC1, fc1b,
                               wh+OFF_FC2, wl+OFF_FC2, fc2b, xnh, xnl);
    gram_gemm<<<528,256,GRAM_SMEM>>>(xnh, xnl, out);
}

// round 17
// speedup vs baseline: 1.0408x; 1.0408x over previous
#include <cuda_runtime.h>
#include <cuda_bf16.h>
#include <mma.h>
#include <cstdint>
using namespace nvcuda;
typedef __nv_bfloat16 bf16;

#define SQ 4096
#define DM 128
#define NH 4
#define NL 3
#define FFD 1024
#define NSPL 4
#define OFF_WQKV 0
#define OFF_WO   147456
#define OFF_W1   196608
#define OFF_W2   589824
#define OFF_FC1  983040
#define OFF_FC2  999424
#define WTOT     1015808

__device__ float g_x[SQ*DM];
__device__ bf16 g_xh[SQ*DM], g_xl[SQ*DM];
__device__ bf16 g_qh[SQ*3*DM];
__device__ bf16 g_f1h[SQ*FFD], g_f1l[SQ*FFD];
__device__ bf16 g_xnh[SQ*DM], g_xnl[SQ*DM];
__device__ bf16 g_wh[WTOT], g_wl[WTOT];
__device__ bf16 g_oat[NSPL*SQ*DM];
__device__ float g_psum[NSPL*NH*SQ];

__device__ __forceinline__ float ex2f(float x){ float y; asm("ex2.approx.f32 %0, %1;" : "=f"(y) : "f"(x)); return y; }
__device__ __forceinline__ uint32_t pack_hi(float a, float b) {
    return (uint32_t)__bfloat16_as_ushort(__float2bfloat16(a))
         | ((uint32_t)__bfloat16_as_ushort(__float2bfloat16(b)) << 16);
}
__device__ __forceinline__ uint32_t pack_lo(float a, float b) {
    float ar = a - __bfloat162float(__float2bfloat16(a));
    float br = b - __bfloat162float(__float2bfloat16(b));
    return pack_hi(ar, br);
}
__device__ __forceinline__ float bflo(uint32_t u){ return __bfloat162float(__ushort_as_bfloat16((unsigned short)(u & 0xFFFFu))); }
__device__ __forceinline__ float bfhi(uint32_t u){ return __bfloat162float(__ushort_as_bfloat16((unsigned short)(u >> 16))); }
__device__ __forceinline__ uint32_t smem_u32(const void* p) {
    uint32_t a;
    asm("{ .reg .u64 t; cvta.to.shared.u64 t, %1; cvt.u32.u64 %0, t; }" : "=r"(a) : "l"(p));
    return a;
}
#define CP_ASYNC16(sa,gp) asm volatile("cp.async.cg.shared.global [%0], [%1], 16;" :: "r"((uint32_t)(sa)), "l"(gp) : "memory")
#define CP_COMMIT() asm volatile("cp.async.commit_group;" ::: "memory")
#define CP_WAIT2() asm volatile("cp.async.wait_group 2;" ::: "memory")
#define CP_WAIT1() asm volatile("cp.async.wait_group 1;" ::: "memory")
#define CP_WAIT0() asm volatile("cp.async.wait_group 0;" ::: "memory")

__device__ __forceinline__ void mma16816(float* c, const uint32_t* a, uint32_t b0, uint32_t b1) {
    asm volatile("mma.sync.aligned.m16n8k16.row.col.f32.bf16.bf16.f32 "
        "{%0,%1,%2,%3},{%4,%5,%6,%7},{%8,%9},{%0,%1,%2,%3};"
        : "+f"(c[0]),"+f"(c[1]),"+f"(c[2]),"+f"(c[3])
        : "r"(a[0]),"r"(a[1]),"r"(a[2]),"r"(a[3]),"r"(b0),"r"(b1));
}
__device__ __forceinline__ void ldsm4(uint32_t* r, uint32_t a) {
    asm volatile("ldmatrix.sync.aligned.m8n8.x4.shared.b16 {%0,%1,%2,%3},[%4];"
        : "=r"(r[0]),"=r"(r[1]),"=r"(r[2]),"=r"(r[3]) : "r"(a));
}
__device__ __forceinline__ void ldsm4t(uint32_t* r, uint32_t a) {
    asm volatile("ldmatrix.sync.aligned.m8n8.x4.trans.shared.b16 {%0,%1,%2,%3},[%4];"
        : "=r"(r[0]),"=r"(r[1]),"=r"(r[2]),"=r"(r[3]) : "r"(a));
}

// ---------- prep ----------
__global__ void prep_kernel(const float* __restrict__ Wqkv, const float* __restrict__ Wo,
                            const float* __restrict__ W1, const float* __restrict__ W2,
                            const float* __restrict__ fc1W, const float* __restrict__ fc2W,
                            const float* __restrict__ src,
                            bf16* __restrict__ wh, bf16* __restrict__ wl,
                            float* __restrict__ x, bf16* __restrict__ xh, bf16* __restrict__ xl) {
    int i = blockIdx.x * 256 + threadIdx.x;
    if (i < WTOT) {
        const float* s; int base;
        if      (i < 196608) { if (i < 147456) { s=Wqkv; base=OFF_WQKV; } else { s=Wo; base=OFF_WO; } }
        else if (i < 983040) { if (i < 589824) { s=W1; base=OFF_W1; } else { s=W2; base=OFF_W2; } }
        else                 { if (i < 999424) { s=fc1W; base=OFF_FC1; } else { s=fc2W; base=OFF_FC2; } }
        float v = s[i - base];
        bf16 h = __float2bfloat16(v);
        wh[i] = h; wl[i] = __float2bfloat16(v - __bfloat162float(h));
    } else if (i < WTOT + SQ*DM) {
        int j = i - WTOT;
        float v = src[j]; x[j] = v;
        bf16 h = __float2bfloat16(v);
        xh[j] = h; xl[j] = __float2bfloat16(v - __bfloat162float(h));
    }
}

// ---------- FFN1 GEMM (128x128 tile, double buffered) ----------
#define GEMM_SMEM 84480
template<int EPI, bool SA, int OUTM>
__global__ __launch_bounds__(256)
void wg_gemm(const bf16* __restrict__ Ah, const bf16* __restrict__ Al,
             const bf16* __restrict__ Bh, const bf16* __restrict__ Bl,
             const float* __restrict__ bias,
             bf16* __restrict__ Ch, bf16* __restrict__ Cl, int N, int K) {
    extern __shared__ char smraw[];
    const int BUFB = (SA ? 4 : 3) * 10240;
    uint32_t sbase = smem_u32(smraw);
    float* Cs = (float*)smraw;
    const int tid = threadIdx.x, w = tid >> 5;
    const int wm = w >> 1, wn = w & 1;
    const int bm = blockIdx.y * 128, bn = blockIdx.x * 128;
    const int ldr = tid >> 1, lh = tid & 1;

    auto issue = [&](int kc, int bi) {
        uint32_t buf = sbase + bi * BUFB;
        int r = tid >> 1, c2 = (tid & 1) * 2;
        uint32_t d = buf + r * 80 + c2 * 16;
        const char* pa = (const char*)(Ah + (size_t)(bm + r) * K + kc) + c2 * 16;
        CP_ASYNC16(d, pa); CP_ASYNC16(d + 16, pa + 16);
        if (SA) {
            const char* pl = (const char*)(Al + (size_t)(bm + r) * K + kc) + c2 * 16;
            CP_ASYNC16(d + 10240, pl); CP_ASYNC16(d + 10240 + 16, pl + 16);
        }
        uint32_t boff = (SA ? 2 : 1) * 10240;
        const char* pb = (const char*)(Bh + (size_t)(bn + r) * K + kc) + c2 * 16;
        CP_ASYNC16(d + boff, pb); CP_ASYNC16(d + boff + 16, pb + 16);
        const char* pbl = (const char*)(Bl + (size_t)(bn + r) * K + kc) + c2 * 16;
        CP_ASYNC16(d + boff + 10240, pbl); CP_ASYNC16(d + boff + 10240 + 16, pbl + 16);
        CP_COMMIT();
    };

    wmma::fragment<wmma::accumulator,16,16,16,float> acc[2][4];
#pragma unroll
    for (int i=0;i<2;i++)
#pragma unroll
        for (int j=0;j<4;j++) wmma::fill_fragment(acc[i][j], 0.f);

    const int nk = K >> 5;
    issue(0, 0);
    for (int c = 0; c < nk; c++) {
        if (c + 1 < nk) { issue((c + 1) * 32, (c + 1) & 1); CP_WAIT1(); }
        else CP_WAIT0();
        __syncthreads();
        bf16* As  = (bf16*)(smraw + (c & 1) * BUFB);
        bf16* Als = As + 5120;
        bf16* Bs  = As + (SA ? 2 : 1) * 5120;
        bf16* Bls = Bs + 5120;
#pragma unroll
        for (int ks = 0; ks < 2; ks++) {
            wmma::fragment<wmma::matrix_a,16,16,16,bf16,wmma::row_major> fa[2], fal[2];
#pragma unroll
            for (int i=0;i<2;i++) {
                wmma::load_matrix_sync(fa[i], As + (wm*32+i*16)*40 + ks*16, 40);
                if (SA) wmma::load_matrix_sync(fal[i], Als + (wm*32+i*16)*40 + ks*16, 40);
            }
#pragma unroll
            for (int j=0;j<4;j++) {
                wmma::fragment<wmma::matrix_b,16,16,16,bf16,wmma::col_major> fb;
                wmma::load_matrix_sync(fb, Bs + (wn*64+j*16)*40 + ks*16, 40);
#pragma unroll
                for (int i=0;i<2;i++) wmma::mma_sync(acc[i][j], fa[i], fb, acc[i][j]);
                if (SA) {
#pragma unroll
                    for (int i=0;i<2;i++) wmma::mma_sync(acc[i][j], fal[i], fb, acc[i][j]);
                }
                wmma::load_matrix_sync(fb, Bls + (wn*64+j*16)*40 + ks*16, 40);
#pragma unroll
                for (int i=0;i<2;i++) wmma::mma_sync(acc[i][j], fa[i], fb, acc[i][j]);
            }
        }
        __syncthreads();
    }
#pragma unroll
    for (int i=0;i<2;i++)
#pragma unroll
        for (int j=0;j<4;j++)
            wmma::store_matrix_sync(Cs + (wm*32+i*16)*132 + wn*64 + j*16, acc[i][j], 132, wmma::mem_row_major);
    __syncthreads();

    const int row = bm + ldr, cb = lh * 64;
#pragma unroll
    for (int c0 = 0; c0 < 64; c0 += 8) {
        float v[8];
#pragma unroll
        for (int i=0;i<8;i++) {
            float xv = Cs[ldr*132 + cb + c0 + i] + bias[bn + cb + c0 + i];
            if (EPI==1) xv = fmaxf(xv, 0.f);
            v[i] = xv;
        }
        *(uint4*)(Ch + (size_t)row*N + bn + cb + c0) =
            make_uint4(pack_hi(v[0],v[1]),pack_hi(v[2],v[3]),pack_hi(v[4],v[5]),pack_hi(v[6],v[7]));
        if (OUTM == 2)
            *(uint4*)(Cl + (size_t)row*N + bn + cb + c0) =
                make_uint4(pack_lo(v[0],v[1]),pack_lo(v[2],v[3]),pack_lo(v[4],v[5]),pack_lo(v[6],v[7]));
    }
}

// ---------- QKV GEMM (64x128 tile, K=128, one-shot) ----------
#define GEMM64N_SMEM 102400
__global__ __launch_bounds__(256)
void wg_gemm64n(const bf16* __restrict__ Ah,
                const bf16* __restrict__ Bh, const bf16* __restrict__ Bl,
                const float* __restrict__ bias, bf16* __restrict__ Ch) {
    extern __shared__ char smraw[];
    const int K = 128, N = 384;
    const int BUFB = 25600;
    uint32_t sbase = smem_u32(smraw);
    float* Cs = (float*)smraw;
    const int tid = threadIdx.x, w = tid >> 5;
    const int wm = w >> 2, wn = w & 3;
    const int bm = blockIdx.y * 64, bn = blockIdx.x * 128;

    auto issue = [&](int kc, int bi) {
        uint32_t buf = sbase + bi * BUFB;
        int r = tid >> 2, c = tid & 3;
        CP_ASYNC16(buf + r * 80 + c * 16, (const char*)(Ah + (size_t)(bm + r) * K + kc) + c * 16);
        int r2 = tid >> 1, c2 = (tid & 1) * 2;
        uint32_t d2 = buf + 5120 + r2 * 80 + c2 * 16;
        const char* pb = (const char*)(Bh + (size_t)(bn + r2) * K + kc) + c2 * 16;
        CP_ASYNC16(d2, pb); CP_ASYNC16(d2 + 16, pb + 16);
        const char* pbl = (const char*)(Bl + (size_t)(bn + r2) * K + kc) + c2 * 16;
        CP_ASYNC16(d2 + 10240, pbl); CP_ASYNC16(d2 + 10240 + 16, pbl + 16);
        CP_COMMIT();
    };

    wmma::fragment<wmma::accumulator,16,16,16,float> acc[2][2];
#pragma unroll
    for (int i=0;i<2;i++)
#pragma unroll
        for (int j=0;j<2;j++) wmma::fill_fragment(acc[i][j], 0.f);

#pragma unroll
    for (int c = 0; c < 4; c++) issue(c * 32, c);
    CP_WAIT0();
    __syncthreads();
#pragma unroll
    for (int c = 0; c < 4; c++) {
        bf16* As  = (bf16*)(smraw + c * BUFB);
        bf16* Bs  = As + 2560;
        bf16* Bls = As + 7680;
#pragma unroll
        for (int ks = 0; ks < 2; ks++) {
            wmma::fragment<wmma::matrix_a,16,16,16,bf16,wmma::row_major> fa[2];
#pragma unroll
            for (int i=0;i<2;i++)
                wmma::load_matrix_sync(fa[i], As + (wm*32+i*16)*40 + ks*16, 40);
#pragma unroll
            for (int j=0;j<2;j++) {
                wmma::fragment<wmma::matrix_b,16,16,16,bf16,wmma::col_major> fb;
                wmma::load_matrix_sync(fb, Bs + (wn*32+j*16)*40 + ks*16, 40);
#pragma unroll
                for (int i=0;i<2;i++) wmma::mma_sync(acc[i][j], fa[i], fb, acc[i][j]);
                wmma::load_matrix_sync(fb, Bls + (wn*32+j*16)*40 + ks*16, 40);
#pragma unroll
                for (int i=0;i<2;i++) wmma::mma_sync(acc[i][j], fa[i], fb, acc[i][j]);
            }
        }
    }
    __syncthreads();
#pragma unroll
    for (int i=0;i<2;i++)
#pragma unroll
        for (int j=0;j<2;j++)
            wmma::store_matrix_sync(Cs + (wm*32+i*16)*132 + wn*32 + j*16, acc[i][j], 132, wmma::mem_row_major);
    __syncthreads();

    const int ldr = tid >> 2, q = tid & 3;
    const int row = bm + ldr, cb = q * 32;
#pragma unroll
    for (int c0 = 0; c0 < 32; c0 += 8) {
        float v[8];
#pragma unroll
        for (int i=0;i<8;i++) v[i] = Cs[ldr*132 + cb + c0 + i] + bias[bn + cb + c0 + i];
        *(uint4*)(Ch + (size_t)row*N + bn + cb + c0) =
            make_uint4(pack_hi(v[0],v[1]),pack_hi(v[2],v[3]),pack_hi(v[4],v[5]),pack_hi(v[6],v[7]));
    }
}

// ---------- O-proj: 32-row tiles (grid 128), per-head combine + B hi-only + residual + LN ----------
#define OPROJ_BUFB 12800
#define OPROJ_SMEM 51200
__global__ __launch_bounds__(256)
void wg_oproj(const bf16* __restrict__ opart, const float* __restrict__ spart,
              const bf16* __restrict__ Bh,
              const float* __restrict__ bias, float* __restrict__ xres,
              const float* __restrict__ gam, const float* __restrict__ bet,
              bf16* __restrict__ outh, bf16* __restrict__ outl) {
    extern __shared__ char smraw[];
    const int K = 128;
    uint32_t sbase = smem_u32(smraw);
    float* Cs = (float*)smraw;
    const int tid = threadIdx.x, w = tid >> 5;
    const int wm = w >> 2, wn = w & 3;
    const int bm = blockIdx.x * 32;

    // B hi-only for all 4 K-chunks
#pragma unroll
    for (int c = 0; c < 4; c++) {
        uint32_t buf = sbase + c * OPROJ_BUFB;
        int r2 = tid >> 1, c2 = (tid & 1) * 2;
        uint32_t d2 = buf + 2560 + r2 * 80 + c2 * 16;
        const char* pb = (const char*)(Bh + (size_t)r2 * K + c * 32) + c2 * 16;
        CP_ASYNC16(d2, pb); CP_ASYNC16(d2 + 16, pb + 16);
        CP_COMMIT();
    }
    // per-head combine: each thread 16 cols of one row (32 rows x 8 thr/row)
    {
        int row = tid >> 3, cseg = (tid & 7) * 16;
        int rg = bm + row, h = cseg >> 5;
        float ssum = 0.f;
#pragma unroll
        for (int z = 0; z < NSPL; z++) ssum += spart[(z*NH + h)*SQ + rg];
        float inv = 1.f / ssum;
        float v[16];
#pragma unroll
        for (int i=0;i<16;i++) v[i] = 0.f;
#pragma unroll
        for (int z = 0; z < NSPL; z++) {
            const uint4* p = (const uint4*)(opart + ((size_t)z*SQ + rg)*DM + cseg);
            uint4 a = p[0], b = p[1];
            uint32_t u[8] = {a.x,a.y,a.z,a.w,b.x,b.y,b.z,b.w};
#pragma unroll
            for (int k=0;k<8;k++) { v[2*k] += bflo(u[k]); v[2*k+1] += bfhi(u[k]); }
        }
#pragma unroll
        for (int i=0;i<16;i++) v[i] *= inv;
        int chunk = cseg >> 5, off = cseg & 31;
        char* dst = smraw + chunk * OPROJ_BUFB + row * 80 + off * 2;
        *(uint4*)dst = make_uint4(pack_hi(v[0],v[1]),pack_hi(v[2],v[3]),pack_hi(v[4],v[5]),pack_hi(v[6],v[7]));
        *(uint4*)(dst + 16) = make_uint4(pack_hi(v[8],v[9]),pack_hi(v[10],v[11]),pack_hi(v[12],v[13]),pack_hi(v[14],v[15]));
    }
    CP_WAIT0();
    __syncthreads();

    wmma::fragment<wmma::accumulator,16,16,16,float> acc[2];
    wmma::fill_fragment(acc[0], 0.f);
    wmma::fill_fragment(acc[1], 0.f);
#pragma unroll
    for (int c = 0; c < 4; c++) {
        bf16* As = (bf16*)(smraw + c * OPROJ_BUFB);
        bf16* Bs = As + 1280;
#pragma unroll
        for (int ks = 0; ks < 2; ks++) {
            wmma::fragment<wmma::matrix_a,16,16,16,bf16,wmma::row_major> fa;
            wmma::load_matrix_sync(fa, As + (wm*16)*40 + ks*16, 40);
#pragma unroll
            for (int j=0;j<2;j++) {
                wmma::fragment<wmma::matrix_b,16,16,16,bf16,wmma::col_major> fb;
                wmma::load_matrix_sync(fb, Bs + (wn*32+j*16)*40 + ks*16, 40);
                wmma::mma_sync(acc[j], fa, fb, acc[j]);
            }
        }
    }
    __syncthreads();
#pragma unroll
    for (int j=0;j<2;j++)
        wmma::store_matrix_sync(Cs + (wm*16)*132 + wn*32 + j*16, acc[j], 132, wmma::mem_row_major);
    __syncthreads();

    const int ldr = tid >> 3, q = tid & 7;
    const int row = bm + ldr, cb = q * 16;
    float v[16];
#pragma unroll
    for (int i=0;i<16;i++) v[i] = Cs[ldr*132 + cb + i] + bias[cb + i];
    float s = 0.f, s2 = 0.f;
#pragma unroll
    for (int i=0;i<16;i++) { v[i] += xres[(size_t)row*DM + cb + i]; s += v[i]; }
#pragma unroll
    for (int i=0;i<16;i++) s2 += v[i]*v[i];
    s  += __shfl_xor_sync(~0u, s, 1);  s  += __shfl_xor_sync(~0u, s, 2);  s  += __shfl_xor_sync(~0u, s, 4);
    s2 += __shfl_xor_sync(~0u, s2, 1); s2 += __shfl_xor_sync(~0u, s2, 2); s2 += __shfl_xor_sync(~0u, s2, 4);
    float mean = s * (1.f/DM);
    float var = s2 * (1.f/DM) - mean*mean;
    float inv = rsqrtf(var + 1e-5f);
#pragma unroll
    for (int i=0;i<16;i++) v[i] = (v[i] - mean) * inv * gam[cb+i] + bet[cb+i];
    float4* dx = (float4*)(xres + (size_t)row*DM + cb);
#pragma unroll
    for (int i=0;i<4;i++) dx[i] = make_float4(v[4*i],v[4*i+1],v[4*i+2],v[4*i+3]);
#pragma unroll
    for (int c0 = 0; c0 < 16; c0 += 8) {
        *(uint4*)(outh + (size_t)row*DM + cb + c0) =
            make_uint4(pack_hi(v[c0],v[c0+1]),pack_hi(v[c0+2],v[c0+3]),pack_hi(v[c0+4],v[c0+5]),pack_hi(v[c0+6],v[c0+7]));
        *(uint4*)(outl + (size_t)row*DM + cb + c0) =
            make_uint4(pack_lo(v[c0],v[c0+1]),pack_lo(v[c0+2],v[c0+3]),pack_lo(v[c0+4],v[c0+5]),pack_lo(v[c0+6],v[c0+7]));
    }
}

// ---------- FFN2 GEMM (32x128 tile, K=1024, 3-stage) + residual + LN ----------
#define GEMM32_SMEM 76800
__global__ __launch_bounds__(256)
void wg_ffn2(const bf16* __restrict__ Ah, const bf16* __restrict__ Al,
             const bf16* __restrict__ Bh, const bf16* __restrict__ Bl,
             const float* __restrict__ bias, float* __restrict__ xres,
             const float* __restrict__ gam, const float* __restrict__ bet,
             bf16* __restrict__ outh, bf16* __restrict__ outl) {
    extern __shared__ char smraw[];
    const int K = 1024;
    const int AB = 5120, BUFB = 25600;
    uint32_t sbase = smem_u32(smraw);
    float* Cs = (float*)smraw;
    const int tid = threadIdx.x, w = tid >> 5;
    const int wm = w >> 2, wn = w & 3;
    const int bm = blockIdx.x * 32;

    auto issue = [&](int kc, int bi) {
        uint32_t buf = sbase + bi * BUFB;
        int m = (tid < 128) ? 0 : 1;
        const bf16* Asrc = m ? Al : Ah;
        int tt = tid & 127;
        int r = tt >> 2, c = tt & 3;
        CP_ASYNC16(buf + m * 2560 + r * 80 + c * 16,
                   (const char*)(Asrc + (size_t)(bm + r) * K + kc) + c * 16);
        int r2 = tid >> 1, c2 = (tid & 1) * 2;
        uint32_t d2 = buf + AB + r2 * 80 + c2 * 16;
        const char* pb = (const char*)(Bh + (size_t)r2 * K + kc) + c2 * 16;
        CP_ASYNC16(d2, pb); CP_ASYNC16(d2 + 16, pb + 16);
        const char* pbl = (const char*)(Bl + (size_t)r2 * K + kc) + c2 * 16;
        CP_ASYNC16(d2 + 10240, pbl); CP_ASYNC16(d2 + 10240 + 16, pbl + 16);
        CP_COMMIT();
    };

    wmma::fragment<wmma::accumulator,16,16,16,float> acc[2];
    wmma::fill_fragment(acc[0], 0.f);
    wmma::fill_fragment(acc[1], 0.f);

    const int nk = 32;
    issue(0, 0); issue(32, 1);
    for (int c = 0; c < nk; c++) {
        if (c + 2 < nk) issue((c + 2) * 32, (c + 2) % 3);
        if (c + 1 < nk) CP_WAIT2(); else CP_WAIT0();
        __syncthreads();
        bf16* As  = (bf16*)(smraw + (c % 3) * BUFB);
        bf16* Als = As + 1280;
        bf16* Bs  = (bf16*)((char*)As + AB);
        bf16* Bls = Bs + 5120;
#pragma unroll
        for (int ks = 0; ks < 2; ks++) {
            wmma::fragment<wmma::matrix_a,16,16,16,bf16,wmma::row_major> fa, fal;
            wmma::load_matrix_sync(fa, As + (wm*16)*40 + ks*16, 40);
            wmma::load_matrix_sync(fal, Als + (wm*16)*40 + ks*16, 40);
#pragma unroll
            for (int j=0;j<2;j++) {
                wmma::fragment<wmma::matrix_b,16,16,16,bf16,wmma::col_major> fb;
                wmma::load_matrix_sync(fb, Bs + (wn*32+j*16)*40 + ks*16, 40);
                wmma::mma_sync(acc[j], fa, fb, acc[j]);
                wmma::mma_sync(acc[j], fal, fb, acc[j]);
                wmma::load_matrix_sync(fb, Bls + (wn*32+j*16)*40 + ks*16, 40);
                wmma::mma_sync(acc[j], fa, fb, acc[j]);
            }
        }
        __syncthreads();
    }
#pragma unroll
    for (int j=0;j<2;j++)
        wmma::store_matrix_sync(Cs + (wm*16)*132 + wn*32 + j*16, acc[j], 132, wmma::mem_row_major);
    __syncthreads();

    const int ldr = tid >> 3, q = tid & 7;
    const int row = bm + ldr, cb = q * 16;
    float v[16];
#pragma unroll
    for (int i=0;i<16;i++) v[i] = Cs[ldr*132 + cb + i] + bias[cb + i];
    float s = 0.f, s2 = 0.f;
#pragma unroll
    for (int i=0;i<16;i++) { v[i] += xres[(size_t)row*DM + cb + i]; s += v[i]; }
#pragma unroll
    for (int i=0;i<16;i++) s2 += v[i]*v[i];
    s  += __shfl_xor_sync(~0u, s, 1);  s  += __shfl_xor_sync(~0u, s, 2);  s  += __shfl_xor_sync(~0u, s, 4);
    s2 += __shfl_xor_sync(~0u, s2, 1); s2 += __shfl_xor_sync(~0u, s2, 2); s2 += __shfl_xor_sync(~0u, s2, 4);
    float mean = s * (1.f/DM);
    float var = s2 * (1.f/DM) - mean*mean;
    float inv = rsqrtf(var + 1e-5f);
#pragma unroll
    for (int i=0;i<16;i++) v[i] = (v[i] - mean) * inv * gam[cb+i] + bet[cb+i];
    float4* dx = (float4*)(xres + (size_t)row*DM + cb);
#pragma unroll
    for (int i=0;i<4;i++) dx[i] = make_float4(v[4*i],v[4*i+1],v[4*i+2],v[4*i+3]);
#pragma unroll
    for (int c0 = 0; c0 < 16; c0 += 8) {
        *(uint4*)(outh + (size_t)row*DM + cb + c0) =
            make_uint4(pack_hi(v[c0],v[c0+1]),pack_hi(v[c0+2],v[c0+3]),pack_hi(v[c0+4],v[c0+5]),pack_hi(v[c0+6],v[c0+7]));
        *(uint4*)(outl + (size_t)row*DM + cb + c0) =
            make_uint4(pack_lo(v[c0],v[c0+1]),pack_lo(v[c0+2],v[c0+3]),pack_lo(v[c0+4],v[c0+5]),pack_lo(v[c0+6],v[c0+7]));
    }
}

// ---------- fused fc1 + fc2 + rownorm ----------
#define FC_SMEM 184320
__global__ __launch_bounds__(256)
void wg_fc(const bf16* __restrict__ xh, const bf16* __restrict__ xl,
           const bf16* __restrict__ B1h, const bf16* __restrict__ B1l,
           const float* __restrict__ b1,
           const bf16* __restrict__ B2h, const bf16* __restrict__ B2l,
           const float* __restrict__ b2,
           bf16* __restrict__ outh, bf16* __restrict__ outl) {
    extern __shared__ char smraw[];
    const int K = 128;
    uint32_t sbase = smem_u32(smraw);
    float* Cs = (float*)smraw;
    const int tid = threadIdx.x, w = tid >> 5;
    const int wm = w >> 2, wn = w & 3;
    const int bm = blockIdx.x * 32;

#pragma unroll
    for (int c = 0; c < 4; c++) {
        int m = (tid < 128) ? 0 : 1;
        const bf16* Asrc = m ? xl : xh;
        int tt = tid & 127;
        int r = tt >> 2, cc = tt & 3;
        CP_ASYNC16(sbase + c*5120 + m*2560 + r*80 + cc*16,
                   (const char*)(Asrc + (size_t)(bm + r) * K + c*32) + cc*16);
        int r2 = tid >> 1, c2 = (tid & 1) * 2;
        uint32_t d1 = sbase + 20480 + c*20480 + r2*80 + c2*16;
        const char* p1 = (const char*)(B1h + (size_t)r2 * K + c*32) + c2*16;
        CP_ASYNC16(d1, p1); CP_ASYNC16(d1 + 16, p1 + 16);
        const char* p1l = (const char*)(B1l + (size_t)r2 * K + c*32) + c2*16;
        CP_ASYNC16(d1 + 10240, p1l); CP_ASYNC16(d1 + 10240 + 16, p1l + 16);
        uint32_t d2 = sbase + 102400 + c*20480 + r2*80 + c2*16;
        const char* p2 = (const char*)(B2h + (size_t)r2 * K + c*32) + c2*16;
        CP_ASYNC16(d2, p2); CP_ASYNC16(d2 + 16, p2 + 16);
        const char* p2l = (const char*)(B2l + (size_t)r2 * K + c*32) + c2*16;
        CP_ASYNC16(d2 + 10240, p2l); CP_ASYNC16(d2 + 10240 + 16, p2l + 16);
        CP_COMMIT();
    }
    CP_WAIT0();
    __syncthreads();

    wmma::fragment<wmma::accumulator,16,16,16,float> acc[2];
    wmma::fill_fragment(acc[0], 0.f);
    wmma::fill_fragment(acc[1], 0.f);
#pragma unroll
    for (int c = 0; c < 4; c++) {
        bf16* As  = (bf16*)(smraw + c*5120);
        bf16* Als = As + 1280;
        bf16* Bs  = (bf16*)(smraw + 20480 + c*20480);
        bf16* Bls = Bs + 5120;
#pragma unroll
        for (int ks = 0; ks < 2; ks++) {
            wmma::fragment<wmma::matrix_a,16,16,16,bf16,wmma::row_major> fa, fal;
            wmma::load_matrix_sync(fa, As + (wm*16)*40 + ks*16, 40);
            wmma::load_matrix_sync(fal, Als + (wm*16)*40 + ks*16, 40);
#pragma unroll
            for (int j=0;j<2;j++) {
                wmma::fragment<wmma::matrix_b,16,16,16,bf16,wmma::col_major> fb;
                wmma::load_matrix_sync(fb, Bs + (wn*32+j*16)*40 + ks*16, 40);
                wmma::mma_sync(acc[j], fa, fb, acc[j]);
                wmma::mma_sync(acc[j], fal, fb, acc[j]);
                wmma::load_matrix_sync(fb, Bls + (wn*32+j*16)*40 + ks*16, 40);
                wmma::mma_sync(acc[j], fa, fb, acc[j]);
            }
        }
    }
    __syncthreads();
#pragma unroll
    for (int j=0;j<2;j++)
        wmma::store_matrix_sync(Cs + (wm*16)*132 + wn*32 + j*16, acc[j], 132, wmma::mem_row_major);
    __syncthreads();

    {
        int row = tid >> 3, q = tid & 7;
        int cb = q * 16;
        float v[16];
#pragma unroll
        for (int i=0;i<16;i++) v[i] = fmaxf(Cs[row*132 + cb + i] + b1[cb + i], 0.f);
        int chunk = cb >> 5, off = cb & 31;
        char* dh = smraw + 20480 + chunk*2560 + row*80 + off*2;
        char* dl = smraw + 30720 + chunk*2560 + row*80 + off*2;
        *(uint4*)dh = make_uint4(pack_hi(v[0],v[1]),pack_hi(v[2],v[3]),pack_hi(v[4],v[5]),pack_hi(v[6],v[7]));
        *(uint4*)(dh+16) = make_uint4(pack_hi(v[8],v[9]),pack_hi(v[10],v[11]),pack_hi(v[12],v[13]),pack_hi(v[14],v[15]));
        *(uint4*)dl = make_uint4(pack_lo(v[0],v[1]),pack_lo(v[2],v[3]),pack_lo(v[4],v[5]),pack_lo(v[6],v[7]));
        *(uint4*)(dl+16) = make_uint4(pack_lo(v[8],v[9]),pack_lo(v[10],v[11]),pack_lo(v[12],v[13]),pack_lo(v[14],v[15]));
    }
    __syncthreads();

    wmma::fill_fragment(acc[0], 0.f);
    wmma::fill_fragment(acc[1], 0.f);
#pragma unroll
    for (int c = 0; c < 4; c++) {
        bf16* As  = (bf16*)(smraw + 20480 + c*2560);
        bf16* Als = (bf16*)(smraw + 30720 + c*2560);
        bf16* Bs  = (bf16*)(smraw + 102400 + c*20480);
        bf16* Bls = Bs + 5120;
#pragma unroll
        for (int ks = 0; ks < 2; ks++) {
            wmma::fragment<wmma::matrix_a,16,16,16,bf16,wmma::row_major> fa, fal;
            wmma::load_matrix_sync(fa, As + (wm*16)*40 + ks*16, 40);
            wmma::load_matrix_sync(fal, Als + (wm*16)*40 + ks*16, 40);
#pragma unroll
            for (int j=0;j<2;j++) {
                wmma::fragment<wmma::matrix_b,16,16,16,bf16,wmma::col_major> fb;
                wmma::load_matrix_sync(fb, Bs + (wn*32+j*16)*40 + ks*16, 40);
                wmma::mma_sync(acc[j], fa, fb, acc[j]);
                wmma::mma_sync(acc[j], fal, fb, acc[j]);
                wmma::load_matrix_sync(fb, Bls + (wn*32+j*16)*40 + ks*16, 40);
                wmma::mma_sync(acc[j], fa, fb, acc[j]);
            }
        }
    }
    __syncthreads();
#pragma unroll
    for (int j=0;j<2;j++)
        wmma::store_matrix_sync(Cs + (wm*16)*132 + wn*32 + j*16, acc[j], 132, wmma::mem_row_major);
    __syncthreads();

    {
        int row = tid >> 3, q = tid & 7;
        int rg = bm + row, cb = q * 16;
        float v[16];
#pragma unroll
        for (int i=0;i<16;i++) v[i] = Cs[row*132 + cb + i] + b2[cb + i];
        float s2 = 0.f;
#pragma unroll
        for (int i=0;i<16;i++) s2 += v[i]*v[i];
        s2 += __shfl_xor_sync(~0u, s2, 1); s2 += __shfl_xor_sync(~0u, s2, 2); s2 += __shfl_xor_sync(~0u, s2, 4);
        float inv = rsqrtf(s2);
#pragma unroll
        for (int i=0;i<16;i++) v[i] *= inv;
#pragma unroll
        for (int c0 = 0; c0 < 16; c0 += 8) {
            *(uint4*)(outh + (size_t)rg*DM + cb + c0) =
                make_uint4(pack_hi(v[c0],v[c0+1]),pack_hi(v[c0+2],v[c0+3]),pack_hi(v[c0+4],v[c0+5]),pack_hi(v[c0+6],v[c0+7]));
            *(uint4*)(outl + (size_t)rg*DM + cb + c0) =
                make_uint4(pack_lo(v[c0],v[c0+1]),pack_lo(v[c0+2],v[c0+3]),pack_lo(v[c0+4],v[c0+5]),pack_lo(v[c0+6],v[c0+7]));
        }
    }
}

// ---------- Gram (triangular, 2 products: hi*hi + hi*lo) ----------
#define GRAM_BUFB 30720
#define GRAM_SMEM 67584
__global__ __launch_bounds__(256)
void gram_gemm(const bf16* __restrict__ Ah, const bf16* __restrict__ Al,
               float* __restrict__ Cf) {
    extern __shared__ char smraw[];
    uint32_t sbase = smem_u32(smraw);
    float* Cs = (float*)smraw;
    const int tid = threadIdx.x, w = tid >> 5;
    const int wm = w >> 1, wn = w & 1;
    int i = blockIdx.x;
    int tm = (int)((sqrtf(8.f*i + 1.f) - 1.f) * 0.5f);
    while ((tm+1)*(tm+2)/2 <= i) tm++;
    while (tm*(tm+1)/2 > i) tm--;
    int tn = i - tm*(tm+1)/2;
    const int bm = tm * 128, bn = tn * 128;
    const int K = DM, N = SQ;
    const int ldr = tid >> 1, lh = tid & 1;

    auto issue = [&](int kc, int bi) {
        uint32_t buf = sbase + bi * GRAM_BUFB;
        int r = tid >> 1, c2 = (tid & 1) * 2;
        uint32_t d = buf + r * 80 + c2 * 16;
        const char* pa = (const char*)(Ah + (size_t)(bm + r) * K + kc) + c2 * 16;
        CP_ASYNC16(d, pa); CP_ASYNC16(d + 16, pa + 16);
        const char* pb = (const char*)(Ah + (size_t)(bn + r) * K + kc) + c2 * 16;
        CP_ASYNC16(d + 10240, pb); CP_ASYNC16(d + 10240 + 16, pb + 16);
        const char* pbl = (const char*)(Al + (size_t)(bn + r) * K + kc) + c2 * 16;
        CP_ASYNC16(d + 20480, pbl); CP_ASYNC16(d + 20480 + 16, pbl + 16);
        CP_COMMIT();
    };

    wmma::fragment<wmma::accumulator,16,16,16,float> acc[2][4];
#pragma unroll
    for (int a=0;a<2;a++)
#pragma unroll
        for (int j=0;j<4;j++) wmma::fill_fragment(acc[a][j], 0.f);

    issue(0, 0);
    for (int c = 0; c < 4; c++) {
        if (c < 3) { issue((c + 1) * 32, (c + 1) & 1); CP_WAIT1(); }
        else CP_WAIT0();
        __syncthreads();
        bf16* As  = (bf16*)(smraw + (c & 1) * GRAM_BUFB);
        bf16* Bs  = As + 5120;
        bf16* Bls = As + 10240;
#pragma unroll
        for (int ks = 0; ks < 2; ks++) {
            wmma::fragment<wmma::matrix_a,16,16,16,bf16,wmma::row_major> fa[2];
#pragma unroll
            for (int a=0;a<2;a++)
                wmma::load_matrix_sync(fa[a], As + (wm*32+a*16)*40 + ks*16, 40);
#pragma unroll
            for (int j=0;j<4;j++) {
                wmma::fragment<wmma::matrix_b,16,16,16,bf16,wmma::col_major> fb;
                wmma::load_matrix_sync(fb, Bs + (wn*64+j*16)*40 + ks*16, 40);
#pragma unroll
                for (int a=0;a<2;a++) wmma::mma_sync(acc[a][j], fa[a], fb, acc[a][j]);
                wmma::load_matrix_sync(fb, Bls + (wn*64+j*16)*40 + ks*16, 40);
#pragma unroll
                for (int a=0;a<2;a++) wmma::mma_sync(acc[a][j], fa[a], fb, acc[a][j]);
            }
        }
        __syncthreads();
    }
#pragma unroll
    for (int a=0;a<2;a++)
#pragma unroll
        for (int j=0;j<4;j++)
            wmma::store_matrix_sync(Cs + (wm*32+a*16)*132 + wn*64 + j*16, acc[a][j], 132, wmma::mem_row_major);
    __syncthreads();

    const int cb = lh * 64;
#pragma unroll
    for (int c0 = 0; c0 < 64; c0 += 4) {
        float4 v;
        v.x = fmaxf(Cs[ldr*132 + cb + c0 + 0], 1e-6f);
        v.y = fmaxf(Cs[ldr*132 + cb + c0 + 1], 1e-6f);
        v.z = fmaxf(Cs[ldr*132 + cb + c0 + 2], 1e-6f);
        v.w = fmaxf(Cs[ldr*132 + cb + c0 + 3], 1e-6f);
        *(float4*)(Cf + (size_t)(bm + ldr)*N + bn + cb + c0) = v;
    }
    if (bm != bn) {
#pragma unroll
        for (int c0 = 0; c0 < 64; c0 += 4) {
            float4 v;
            v.x = fmaxf(Cs[(cb + c0 + 0)*132 + ldr], 1e-6f);
            v.y = fmaxf(Cs[(cb + c0 + 1)*132 + ldr], 1e-6f);
            v.z = fmaxf(Cs[(cb + c0 + 2)*132 + ldr], 1e-6f);
            v.w = fmaxf(Cs[(cb + c0 + 3)*132 + ldr], 1e-6f);
            *(float4*)(Cf + (size_t)(bn + ldr)*N + bm + cb + c0) = v;
        }
    }
}

// ---------- FA2 attention, split-K (4 splits), bf16 partials ----------
#define ATTN_SMEM 51200
__global__ __launch_bounds__(256)
void fa_attn(const bf16* __restrict__ q, bf16* __restrict__ opart, float* __restrict__ spart) {
    extern __shared__ char smraw[];
    uint32_t sb = smem_u32(smraw);
    const uint32_t Qs = sb, K0 = sb + 10240, V0 = sb + 30720;
    const int tid = threadIdx.x, w = tid >> 5, lane = tid & 31;
    const int g = lane >> 2, t = lane & 3;
    const int qt = blockIdx.x, h = blockIdx.y, z = blockIdx.z;
    const int kt0 = z * 8;
    const float C = 0.2550368953428811f;

    auto issue_kv = [&](int kt, int bi) {
        int r = tid >> 1, c2 = (tid & 1) * 2;
        const char* srck = (const char*)(q + (size_t)(kt*128 + r) * 384 + 128 + h*32) + c2*16;
        const char* srcv = (const char*)(q + (size_t)(kt*128 + r) * 384 + 256 + h*32) + c2*16;
        uint32_t kd = K0 + bi*10240 + r*80 + c2*16;
        uint32_t vd = V0 + bi*10240 + r*80 + c2*16;
        CP_ASYNC16(kd, srck); CP_ASYNC16(kd+16, srck+16);
        CP_ASYNC16(vd, srcv); CP_ASYNC16(vd+16, srcv+16);
        CP_COMMIT();
    };

    {
        int r = tid >> 1, c2 = (tid & 1) * 2;
        const char* srcq = (const char*)(q + (size_t)(qt*128 + r) * 384 + h*32) + c2*16;
        uint32_t qd = Qs + r*80 + c2*16;
        CP_ASYNC16(qd, srcq); CP_ASYNC16(qd+16, srcq+16);
        CP_COMMIT();
    }
    issue_kv(kt0, 0);

    uint32_t qf[2][4];
    float oacc[4][4];
#pragma unroll
    for (int i=0;i<4;i++)
#pragma unroll
        for (int j=0;j<4;j++) oacc[i][j] = 0.f;
    float sum_lo = 0.f, sum_hi = 0.f;

    for (int ki = 0; ki < 8; ki++) {
        int b = ki & 1;
        if (ki < 7) { issue_kv(kt0 + ki + 1, b ^ 1); CP_WAIT1(); }
        else CP_WAIT0();
        __syncthreads();
        if (ki == 0) {
#pragma unroll
            for (int s = 0; s < 2; s++) {
                uint32_t a = Qs + (uint32_t)(w*16 + ((lane>>3)&1)*8 + (lane&7))*80
                           + (uint32_t)(s*16 + (lane>>4)*8)*2;
                ldsm4(qf[s], a);
            }
        }
        uint32_t ks = K0 + b*10240, vs = V0 + b*10240;
#pragma unroll
        for (int j2 = 0; j2 < 8; j2++) {
            float sa[2][4] = {{0.f,0.f,0.f,0.f},{0.f,0.f,0.f,0.f}};
#pragma unroll
            for (int jj = 0; jj < 2; jj++) {
                int j = j2 * 2 + jj;
                uint32_t kf[4];
                uint32_t ka = ks + (uint32_t)(j*8 + (lane&7))*80 + (uint32_t)((lane>>3)*8)*2;
                ldsm4(kf, ka);
                mma16816(sa[jj], qf[0], kf[0], kf[1]);
                mma16816(sa[jj], qf[1], kf[2], kf[3]);
            }
            float p0 = ex2f(sa[0][0]*C), p1 = ex2f(sa[0][1]*C);
            float p2 = ex2f(sa[0][2]*C), p3 = ex2f(sa[0][3]*C);
            float p4 = ex2f(sa[1][0]*C), p5 = ex2f(sa[1][1]*C);
            float p6 = ex2f(sa[1][2]*C), p7 = ex2f(sa[1][3]*C);
            sum_lo += p0 + p1 + p4 + p5;
            sum_hi += p2 + p3 + p6 + p7;
            uint32_t af[4] = { pack_hi(p0,p1), pack_hi(p2,p3), pack_hi(p4,p5), pack_hi(p6,p7) };
#pragma unroll
            for (int half = 0; half < 2; half++) {
                uint32_t vf[4];
                uint32_t va = vs + (uint32_t)(j2*16 + ((lane>>3)&1)*8 + (lane&7))*80
                            + (uint32_t)((half*2 + (lane>>4))*8)*2;
                ldsm4t(vf, va);
                mma16816(oacc[half*2],     af, vf[0], vf[1]);
                mma16816(oacc[half*2 + 1], af, vf[2], vf[3]);
            }
        }
        __syncthreads();
    }
    sum_lo += __shfl_xor_sync(~0u, sum_lo, 1); sum_lo += __shfl_xor_sync(~0u, sum_lo, 2);
    sum_hi += __shfl_xor_sync(~0u, sum_hi, 1); sum_hi += __shfl_xor_sync(~0u, sum_hi, 2);
    int rlo = qt*128 + w*16 + g, rhi = rlo + 8;
    if (t == 0) {
        spart[(z*NH + h)*SQ + rlo] = sum_lo;
        spart[(z*NH + h)*SQ + rhi] = sum_hi;
    }
    bf16* oz = opart + (size_t)z*SQ*DM;
#pragma unroll
    for (int jd = 0; jd < 4; jd++) {
        *(uint32_t*)(oz + (size_t)rlo*DM + h*32 + jd*8 + 2*t) = pack_hi(oacc[jd][0], oacc[jd][1]);
        *(uint32_t*)(oz + (size_t)rhi*DM + h*32 + jd*8 + 2*t) = pack_hi(oacc[jd][2], oacc[jd][3]);
    }
}

// ---------- launch ----------
extern "C" void kernel_launch(void* const* d_in, const int* in_sizes, int n_in,
                              void* d_out, int out_size) {
    const float* src  = (const float*)d_in[0];
    const float* Wqkv = (const float*)d_in[1];
    const float* bqkv = (const float*)d_in[2];
    const float* Wo   = (const float*)d_in[3];
    const float* bo   = (const float*)d_in[4];
    const float* ln1g = (const float*)d_in[5];
    const float* ln1b = (const float*)d_in[6];
    const float* W1   = (const float*)d_in[7];
    const float* b1   = (const float*)d_in[8];
    const float* W2   = (const float*)d_in[9];
    const float* b2   = (const float*)d_in[10];
    const float* ln2g = (const float*)d_in[11];
    const float* ln2b = (const float*)d_in[12];
    const float* fc1W = (const float*)d_in[13];
    const float* fc1b = (const float*)d_in[14];
    const float* fc2W = (const float*)d_in[15];
    const float* fc2b = (const float*)d_in[16];
    float* out = (float*)d_out;

    float *x, *psum; bf16 *xh, *xl, *qh, *f1h, *f1l, *xnh, *xnl, *wh, *wl, *oat;
    cudaGetSymbolAddress((void**)&x, g_x);
    cudaGetSymbolAddress((void**)&xh, g_xh);   cudaGetSymbolAddress((void**)&xl, g_xl);
    cudaGetSymbolAddress((void**)&qh, g_qh);
    cudaGetSymbolAddress((void**)&f1h, g_f1h); cudaGetSymbolAddress((void**)&f1l, g_f1l);
    cudaGetSymbolAddress((void**)&xnh, g_xnh); cudaGetSymbolAddress((void**)&xnl, g_xnl);
    cudaGetSymbolAddress((void**)&wh, g_wh);   cudaGetSymbolAddress((void**)&wl, g_wl);
    cudaGetSymbolAddress((void**)&oat, g_oat); cudaGetSymbolAddress((void**)&psum, g_psum);

    cudaFuncSetAttribute(wg_gemm<1,true,2>,  cudaFuncAttributeMaxDynamicSharedMemorySize, GEMM_SMEM);
    cudaFuncSetAttribute(wg_gemm64n,         cudaFuncAttributeMaxDynamicSharedMemorySize, GEMM64N_SMEM);
    cudaFuncSetAttribute(wg_oproj,           cudaFuncAttributeMaxDynamicSharedMemorySize, OPROJ_SMEM);
    cudaFuncSetAttribute(wg_ffn2,            cudaFuncAttributeMaxDynamicSharedMemorySize, GEMM32_SMEM);
    cudaFuncSetAttribute(wg_fc,              cudaFuncAttributeMaxDynamicSharedMemorySize, FC_SMEM);
    cudaFuncSetAttribute(gram_gemm, cudaFuncAttributeMaxDynamicSharedMemorySize, GRAM_SMEM);
    cudaFuncSetAttribute(fa_attn, cudaFuncAttributeMaxDynamicSharedMemorySize, ATTN_SMEM);

    prep_kernel<<<(WTOT + SQ*DM)/256, 256>>>(Wqkv, Wo, W1, W2, fc1W, fc2W, src,
                                             wh, wl, x, xh, xl);

    for (int l = 0; l < NL; l++) {
        wg_gemm64n<<<dim3(3,64),256,GEMM64N_SMEM>>>(
            xh, wh+OFF_WQKV+(size_t)l*49152, wl+OFF_WQKV+(size_t)l*49152,
            bqkv + l*384, qh);
        fa_attn<<<dim3(32,NH,NSPL),256,ATTN_SMEM>>>(qh, oat, psum);
        wg_oproj<<<128,256,OPROJ_SMEM>>>(
            oat, psum, wh+OFF_WO+(size_t)l*16384,
            bo + l*DM, x, ln1g + l*DM, ln1b + l*DM, xh, xl);
        wg_gemm<1,true,2><<<dim3(8,32),256,GEMM_SMEM>>>(
            xh, xl, wh+OFF_W1+(size_t)l*131072, wl+OFF_W1+(size_t)l*131072,
            b1 + l*FFD, f1h, f1l, FFD, 128);
        wg_ffn2<<<128,256,GEMM32_SMEM>>>(
            f1h, f1l, wh+OFF_W2+(size_t)l*131072, wl+OFF_W2+(size_t)l*131072,
            b2 + l*DM, x, ln2g + l*DM, ln2b + l*DM, xh, xl);
    }
    wg_fc<<<128,256,FC_SMEM>>>(xh, xl, wh+OFF_FC1, wl+OFF_FC1, fc1b,
                               wh+OFF_FC2, wl+OFF_FC2, fc2b, xnh, xnl);
    gram_gemm<<<528,256,GRAM_SMEM>>>(xnh, xnl, out);
}